// round 8
// baseline (speedup 1.0000x reference)
#include <cuda_runtime.h>
#include <cstdint>
#include <cstddef>

#define B_DIM 8
#define S_LEN 2048
#define D_EMB 512
#define H_NUM 8
#define D_HEAD 64
#define NTOK (B_DIM * S_LEN)          // 16384

typedef unsigned long long u64;

// ---- packed fp32 helpers (fma.rn.f32x2: 2 fp32 FMAs per instruction) -------
__device__ __forceinline__ u64 pk(float lo, float hi) {
    u64 r; asm("mov.b64 %0, {%1, %2};" : "=l"(r) : "f"(lo), "f"(hi)); return r;
}
__device__ __forceinline__ void upk(float& lo, float& hi, u64 v) {
    asm("mov.b64 {%0, %1}, %2;" : "=f"(lo), "=f"(hi) : "l"(v));
}
__device__ __forceinline__ u64 fma2(u64 a, u64 b, u64 c) {
    u64 r; asm("fma.rn.f32x2 %0, %1, %2, %3;" : "=l"(r) : "l"(a), "l"(b), "l"(c));
    return r;
}
__device__ __forceinline__ u64 mul2(u64 a, u64 b) {
    u64 r; asm("mul.rn.f32x2 %0, %1, %2;" : "=l"(r) : "l"(a), "l"(b));
    return r;
}

// ---------------- scratch (static device globals; no runtime alloc) ----------
__device__ float g_q  [(size_t)NTOK * D_EMB];        // 32 MB
__device__ float g_kv [(size_t)NTOK * 2 * D_EMB];    // 64 MB
__device__ float g_att[(size_t)NTOK * D_EMB];        // 32 MB
__device__ float g_y  [(size_t)NTOK * D_EMB];        // 32 MB
__device__ float g_maskf[B_DIM * S_LEN];             // 64 KB

// ---------------- mask dtype detection + expansion ---------------------------
__global__ void mask_expand_kernel(const void* __restrict__ mraw,
                                   float* __restrict__ mf)
{
    const int tid = threadIdx.x;
    const unsigned int* w = (const unsigned int*)mraw;
    int lf_u8 = 0, lf_i32 = 0, lf_f32 = 0, lf_b16 = 0;
    for (int i = tid; i < 4096; i += 256) {
        unsigned int x = w[i];
        if (x == 0u) continue;
        if (x == 0x3F800000u) { lf_f32 = 1; continue; }          // fp32 1.0
        if (x == 0x00003F80u || x == 0x3F803F80u) { lf_b16 = 1; continue; }
        if (x == 1u) { lf_i32 = 1; continue; }
        bool u8ok = true;
        #pragma unroll
        for (int s = 0; s < 32; s += 8) {
            unsigned int byte = (x >> s) & 0xFFu;
            if (byte > 1u) u8ok = false;
        }
        if (u8ok) lf_u8 = 1;
    }
    int any_b16 = __syncthreads_or(lf_b16);
    int any_f32 = __syncthreads_or(lf_f32);
    int any_u8  = __syncthreads_or(lf_u8);
    int any_i32 = __syncthreads_or(lf_i32);

    int mode;                 // 0=u8, 1=i32, 2=f32, 3=bf16
    if (any_b16)      mode = 3;
    else if (any_f32) mode = 2;
    else if (any_u8)  mode = 0;
    else if (any_i32) mode = 1;
    else              mode = 0;

    for (int j = tid; j < B_DIM * S_LEN; j += 256) {
        bool m;
        if (mode == 0)      m = ((const unsigned char*) mraw)[j] != 0;
        else if (mode == 1) m = ((const int*)           mraw)[j] != 0;
        else if (mode == 2) m = ((const float*)         mraw)[j] != 0.0f;
        else                m = ((const unsigned short*)mraw)[j] != 0;
        mf[j] = m ? 1.0f : 0.0f;
    }
}

// ---------------- fp32 SGEMM (FFMA2): C = A @ W (+bias)(+residual) -----------
__global__ __launch_bounds__(256)
void sgemm_kernel(const float* __restrict__ A, const float* __restrict__ W,
                  float* __restrict__ C, int M, int N, int K,
                  const float* __restrict__ bias,
                  const float* __restrict__ residual)
{
    __shared__ float As[16][132];   // As[k][m]
    __shared__ float Ws[16][132];   // Ws[k][n]

    const int tid = threadIdx.x;
    const int m0 = blockIdx.y * 128;
    const int n0 = blockIdx.x * 128;
    const int ty = tid >> 4, tx = tid & 15;

    u64 accp[8][4];
    #pragma unroll
    for (int i = 0; i < 8; i++)
        #pragma unroll
        for (int j = 0; j < 4; j++) accp[i][j] = 0ull;

    const int alr = tid >> 2;
    const int alc = (tid & 3) << 2;
    const int wlr = tid >> 5;
    const int wlc = (tid & 31) << 2;

    for (int kb = 0; kb < K; kb += 16) {
        #pragma unroll
        for (int p = 0; p < 2; p++) {
            float4 a = *(const float4*)(A + (size_t)(m0 + alr + p * 64) * K + kb + alc);
            As[alc + 0][alr + p * 64] = a.x;
            As[alc + 1][alr + p * 64] = a.y;
            As[alc + 2][alr + p * 64] = a.z;
            As[alc + 3][alr + p * 64] = a.w;
            float4 wv = *(const float4*)(W + (size_t)(kb + wlr + p * 8) * N + n0 + wlc);
            *(float4*)&Ws[wlr + p * 8][wlc] = wv;
        }
        __syncthreads();
        #pragma unroll
        for (int kk = 0; kk < 16; kk++) {
            float af[8];
            *(float4*)(af + 0) = *(const float4*)&As[kk][ty * 8 + 0];
            *(float4*)(af + 4) = *(const float4*)&As[kk][ty * 8 + 4];
            ulonglong2 w0 = *(const ulonglong2*)&Ws[kk][tx * 8 + 0];
            ulonglong2 w1 = *(const ulonglong2*)&Ws[kk][tx * 8 + 4];
            #pragma unroll
            for (int i = 0; i < 8; i++) {
                const u64 ad = pk(af[i], af[i]);
                accp[i][0] = fma2(ad, w0.x, accp[i][0]);
                accp[i][1] = fma2(ad, w0.y, accp[i][1]);
                accp[i][2] = fma2(ad, w1.x, accp[i][2]);
                accp[i][3] = fma2(ad, w1.y, accp[i][3]);
            }
        }
        __syncthreads();
    }

    #pragma unroll
    for (int i = 0; i < 8; i++) {
        const int row = m0 + ty * 8 + i;
        #pragma unroll
        for (int half = 0; half < 2; half++) {
            const int col = n0 + tx * 8 + half * 4;
            float4 c;
            upk(c.x, c.y, accp[i][half * 2 + 0]);
            upk(c.z, c.w, accp[i][half * 2 + 1]);
            if (bias) {
                float4 bb = *(const float4*)(bias + col);
                c.x += bb.x; c.y += bb.y; c.z += bb.z; c.w += bb.w;
            }
            if (residual) {
                float4 r = *(const float4*)(residual + (size_t)row * N + col);
                c.x += r.x; c.y += r.y; c.z += r.z; c.w += r.w;
            }
            *(float4*)(C + (size_t)row * N + col) = c;
        }
    }
}

// ---------------- flash attention (128q x 128k, FFMA2 math) ------------------
#define TQ 128
#define TK 128
#define QSTR 132
#define VSTR 68
#define ATTN_SMEM ((2 * 64 * QSTR + TK * VSTR + TQ * QSTR + 3 * TQ) * (int)sizeof(float))

__global__ __launch_bounds__(256, 1)
void attn_kernel(const float* __restrict__ bias,
                 const float* __restrict__ gamma_f)
{
    extern __shared__ float sm[];
    float* Qs = sm;                        // [64][QSTR]  ([d][q])
    float* Ks = Qs + 64 * QSTR;            // [64][QSTR]  ([d][k])
    float* Vs = Ks + 64 * QSTR;            // [TK][VSTR]  ([k][c])
    float* Ss = Vs + TK * VSTR;            // [TQ][QSTR]
    float* m_s    = Ss + TQ * QSTR;        // [TQ]
    float* l_s    = m_s + TQ;              // [TQ]
    float* corr_s = l_s + TQ;              // [TQ]

    const int tid = threadIdx.x;
    const int qt = blockIdx.x, h = blockIdx.y, b = blockIdx.z;
    const float g = gamma_f[h];
    const int nq0 = b * S_LEN + qt * TQ;
    const int ty = tid >> 4, tx = tid & 15;
    const int c4 = tx << 2;

    // ---- load Q transposed, pre-scaled by 1/sqrt(64)=0.125 (exact) ----
    #pragma unroll
    for (int p = 0; p < 8; p++) {
        const int row = ty + p * 16;
        float4 v = *(const float4*)(g_q + (size_t)(nq0 + row) * D_EMB + h * D_HEAD + c4);
        Qs[(c4 + 0) * QSTR + row] = v.x * 0.125f;
        Qs[(c4 + 1) * QSTR + row] = v.y * 0.125f;
        Qs[(c4 + 2) * QSTR + row] = v.z * 0.125f;
        Qs[(c4 + 3) * QSTR + row] = v.w * 0.125f;
    }
    if (tid < TQ) { m_s[tid] = -1e30f; l_s[tid] = 0.0f; }

    u64 Op[16];                 // [i][c2]: rows ty*8+i, col pairs (tx*4+{0,1},{2,3})
    #pragma unroll
    for (int e = 0; e < 16; e++) Op[e] = 0ull;

    for (int kt = 0; kt < S_LEN / TK; kt++) {
        __syncthreads();
        // ---- load K (transposed) and V ----
        #pragma unroll
        for (int p = 0; p < 8; p++) {
            const int row = ty + p * 16;
            const size_t nk = (size_t)(b * S_LEN + kt * TK + row);
            float4 kv = *(const float4*)(g_kv + nk * (2 * D_EMB) + h * D_HEAD + c4);
            Ks[(c4 + 0) * QSTR + row] = kv.x;
            Ks[(c4 + 1) * QSTR + row] = kv.y;
            Ks[(c4 + 2) * QSTR + row] = kv.z;
            Ks[(c4 + 3) * QSTR + row] = kv.w;
            float4 vv = *(const float4*)(g_kv + nk * (2 * D_EMB) + D_EMB + h * D_HEAD + c4);
            *(float4*)(Vs + row * VSTR + c4) = vv;
        }
        __syncthreads();

        // ---- S = Q K^T : 8x8 micro-tile, packed pairs over k-cols ----
        u64 accp[32];
        #pragma unroll
        for (int e = 0; e < 32; e++) accp[e] = 0ull;
        #pragma unroll 4
        for (int d = 0; d < 64; d++) {
            float qf[8];
            *(float4*)(qf + 0) = *(const float4*)(Qs + d * QSTR + ty * 8 + 0);
            *(float4*)(qf + 4) = *(const float4*)(Qs + d * QSTR + ty * 8 + 4);
            ulonglong2 k0 = *(const ulonglong2*)(Ks + d * QSTR + tx * 8 + 0);
            ulonglong2 k1 = *(const ulonglong2*)(Ks + d * QSTR + tx * 8 + 4);
            #pragma unroll
            for (int i = 0; i < 8; i++) {
                const u64 qd = pk(qf[i], qf[i]);
                accp[i * 4 + 0] = fma2(qd, k0.x, accp[i * 4 + 0]);
                accp[i * 4 + 1] = fma2(qd, k0.y, accp[i * 4 + 1]);
                accp[i * 4 + 2] = fma2(qd, k1.x, accp[i * 4 + 2]);
                accp[i * 4 + 3] = fma2(qd, k1.y, accp[i * 4 + 3]);
            }
        }

        // ---- gamma*bias + mask, stage raw scores to Ss ----
        {
            float mk[8];
            *(float4*)(mk + 0) = *(const float4*)(g_maskf + b * S_LEN + kt * TK + tx * 8 + 0);
            *(float4*)(mk + 4) = *(const float4*)(g_maskf + b * S_LEN + kt * TK + tx * 8 + 4);
            #pragma unroll
            for (int i = 0; i < 8; i++) {
                float sa[8];
                upk(sa[0], sa[1], accp[i * 4 + 0]);
                upk(sa[2], sa[3], accp[i * 4 + 1]);
                upk(sa[4], sa[5], accp[i * 4 + 2]);
                upk(sa[6], sa[7], accp[i * 4 + 3]);
                const int qi = qt * TQ + ty * 8 + i;
                const float* bp = bias + ((size_t)b * S_LEN + qi) * S_LEN + kt * TK + tx * 8;
                float4 b0 = *(const float4*)(bp + 0);
                float4 b1 = *(const float4*)(bp + 4);
                float4 o0, o1;
                o0.x = (mk[0] != 0.0f) ? -1e9f : fmaf(g, b0.x, sa[0]);
                o0.y = (mk[1] != 0.0f) ? -1e9f : fmaf(g, b0.y, sa[1]);
                o0.z = (mk[2] != 0.0f) ? -1e9f : fmaf(g, b0.z, sa[2]);
                o0.w = (mk[3] != 0.0f) ? -1e9f : fmaf(g, b0.w, sa[3]);
                o1.x = (mk[4] != 0.0f) ? -1e9f : fmaf(g, b1.x, sa[4]);
                o1.y = (mk[5] != 0.0f) ? -1e9f : fmaf(g, b1.y, sa[5]);
                o1.z = (mk[6] != 0.0f) ? -1e9f : fmaf(g, b1.z, sa[6]);
                o1.w = (mk[7] != 0.0f) ? -1e9f : fmaf(g, b1.w, sa[7]);
                *(float4*)(Ss + (ty * 8 + i) * QSTR + tx * 8 + 0) = o0;
                *(float4*)(Ss + (ty * 8 + i) * QSTR + tx * 8 + 4) = o1;
            }
        }
        __syncthreads();

        // ---- online softmax: 2 threads per row, 64 cols each ----
        {
            const int r = tid >> 1, hf = tid & 1;
            float* rp = Ss + r * QSTR + hf * 64;
            float tmax = -1e30f;
            #pragma unroll
            for (int k4 = 0; k4 < 64; k4 += 4) {
                float4 v = *(const float4*)(rp + k4);
                tmax = fmaxf(tmax, fmaxf(fmaxf(v.x, v.y), fmaxf(v.z, v.w)));
            }
            tmax = fmaxf(tmax, __shfl_xor_sync(0xffffffffu, tmax, 1));
            const float mold = m_s[r];
            const float mnew = fmaxf(mold, tmax);
            const float corr = __expf(mold - mnew);
            float ps = 0.0f;
            #pragma unroll
            for (int k4 = 0; k4 < 64; k4 += 4) {
                float4 v = *(const float4*)(rp + k4);
                v.x = __expf(v.x - mnew);
                v.y = __expf(v.y - mnew);
                v.z = __expf(v.z - mnew);
                v.w = __expf(v.w - mnew);
                ps += v.x + v.y + v.z + v.w;
                *(float4*)(rp + k4) = v;
            }
            ps += __shfl_xor_sync(0xffffffffu, ps, 1);
            if (hf == 0) {
                m_s[r] = mnew;
                l_s[r] = l_s[r] * corr + ps;
                corr_s[r] = corr;
            }
        }
        __syncthreads();

        // ---- rescale O, then O += P @ V (packed pairs over head-cols) ----
        #pragma unroll
        for (int i = 0; i < 8; i++) {
            const u64 cd = pk(corr_s[ty * 8 + i], corr_s[ty * 8 + i]);
            Op[i * 2 + 0] = mul2(Op[i * 2 + 0], cd);
            Op[i * 2 + 1] = mul2(Op[i * 2 + 1], cd);
        }
        #pragma unroll 2
        for (int j = 0; j < TK; j += 4) {
            ulonglong2 v0 = *(const ulonglong2*)(Vs + (j + 0) * VSTR + tx * 4);
            ulonglong2 v1 = *(const ulonglong2*)(Vs + (j + 1) * VSTR + tx * 4);
            ulonglong2 v2 = *(const ulonglong2*)(Vs + (j + 2) * VSTR + tx * 4);
            ulonglong2 v3 = *(const ulonglong2*)(Vs + (j + 3) * VSTR + tx * 4);
            #pragma unroll
            for (int i = 0; i < 8; i++) {
                float4 pp = *(const float4*)(Ss + (ty * 8 + i) * QSTR + j);
                u64 a0 = Op[i * 2 + 0], a1 = Op[i * 2 + 1];
                u64 pd;
                pd = pk(pp.x, pp.x);
                a0 = fma2(pd, v0.x, a0); a1 = fma2(pd, v0.y, a1);
                pd = pk(pp.y, pp.y);
                a0 = fma2(pd, v1.x, a0); a1 = fma2(pd, v1.y, a1);
                pd = pk(pp.z, pp.z);
                a0 = fma2(pd, v2.x, a0); a1 = fma2(pd, v2.y, a1);
                pd = pk(pp.w, pp.w);
                a0 = fma2(pd, v3.x, a0); a1 = fma2(pd, v3.y, a1);
                Op[i * 2 + 0] = a0; Op[i * 2 + 1] = a1;
            }
        }
    }

    // ---- epilogue: normalize and store ----
    #pragma unroll
    for (int i = 0; i < 8; i++) {
        const int row = ty * 8 + i;
        const float inv = 1.0f / l_s[row];
        const u64 invd = pk(inv, inv);
        const u64 r0 = mul2(Op[i * 2 + 0], invd);
        const u64 r1 = mul2(Op[i * 2 + 1], invd);
        float4 o;
        upk(o.x, o.y, r0);
        upk(o.z, o.w, r1);
        *(float4*)(g_att + (size_t)(nq0 + row) * D_EMB + h * D_HEAD + tx * 4) = o;
    }
}

// ---------------- layernorm: one warp per row of 512 -------------------------
__global__ void ln_kernel(const float* __restrict__ y,
                          const float* __restrict__ lng,
                          const float* __restrict__ lnb,
                          float* __restrict__ out)
{
    const int warp = threadIdx.x >> 5, lane = threadIdx.x & 31;
    const int row = blockIdx.x * 8 + warp;
    const float* yr = y + (size_t)row * D_EMB;

    float v[16];
    #pragma unroll
    for (int c = 0; c < 4; c++)
        *(float4*)(v + c * 4) = *(const float4*)(yr + c * 128 + lane * 4);

    float s = 0.0f;
    #pragma unroll
    for (int e = 0; e < 16; e++) s += v[e];
    #pragma unroll
    for (int off = 16; off > 0; off >>= 1) s += __shfl_xor_sync(0xffffffffu, s, off);
    const float mu = s * (1.0f / 512.0f);

    float sq = 0.0f;
    #pragma unroll
    for (int e = 0; e < 16; e++) { const float d = v[e] - mu; sq = fmaf(d, d, sq); }
    #pragma unroll
    for (int off = 16; off > 0; off >>= 1) sq += __shfl_xor_sync(0xffffffffu, sq, off);
    const float rstd = rsqrtf(sq * (1.0f / 512.0f) + 1e-5f);

    #pragma unroll
    for (int c = 0; c < 4; c++) {
        const int col = c * 128 + lane * 4;
        float4 gg = *(const float4*)(lng + col);
        float4 bb = *(const float4*)(lnb + col);
        float4 o;
        o.x = (v[c*4+0] - mu) * rstd * gg.x + bb.x;
        o.y = (v[c*4+1] - mu) * rstd * gg.y + bb.y;
        o.z = (v[c*4+2] - mu) * rstd * gg.z + bb.z;
        o.w = (v[c*4+3] - mu) * rstd * gg.w + bb.w;
        *(float4*)(out + (size_t)row * D_EMB + col) = o;
    }
}

// ---------------- launch ------------------------------------------------------
extern "C" void kernel_launch(void* const* d_in, const int* in_sizes, int n_in,
                              void* d_out, int out_size)
{
    (void)in_sizes; (void)n_in; (void)out_size;
    const float* x_p     = (const float*)d_in[0];
    const float* x_pcre  = (const float*)d_in[1];
    const float* bias    = (const float*)d_in[2];
    const void*  mask    = d_in[3];
    const float* Wq      = (const float*)d_in[4];
    const float* Wkv     = (const float*)d_in[5];
    const float* Wff     = (const float*)d_in[6];
    const float* bff     = (const float*)d_in[7];
    const float* gamma_f = (const float*)d_in[8];
    const float* ln_g    = (const float*)d_in[9];
    const float* ln_b    = (const float*)d_in[10];
    float* out = (float*)d_out;

    float *gq, *gkv, *gatt, *gy, *gmf;
    cudaGetSymbolAddress((void**)&gq,  g_q);
    cudaGetSymbolAddress((void**)&gkv, g_kv);
    cudaGetSymbolAddress((void**)&gatt,g_att);
    cudaGetSymbolAddress((void**)&gy,  g_y);
    cudaGetSymbolAddress((void**)&gmf, g_maskf);

    cudaFuncSetAttribute(attn_kernel, cudaFuncAttributeMaxDynamicSharedMemorySize,
                         ATTN_SMEM);

    mask_expand_kernel<<<1, 256>>>(mask, gmf);
    sgemm_kernel<<<dim3( 4, 128), 256>>>(x_p,    Wq,  gq,  NTOK,  512, 512, nullptr, nullptr);
    sgemm_kernel<<<dim3( 8, 128), 256>>>(x_pcre, Wkv, gkv, NTOK, 1024, 512, nullptr, nullptr);
    attn_kernel<<<dim3(S_LEN / TQ, H_NUM, B_DIM), 256, ATTN_SMEM>>>(bias, gamma_f);
    sgemm_kernel<<<dim3( 4, 128), 256>>>(gatt,   Wff, gy,  NTOK,  512, 512, bff, x_p);
    ln_kernel<<<NTOK / 8, 256>>>(gy, ln_g, ln_b, out);
}

// round 9
// speedup vs baseline: 1.3636x; 1.3636x over previous
#include <cuda_runtime.h>
#include <cuda_bf16.h>
#include <cstdint>
#include <cstddef>

#define B_DIM 8
#define S_LEN 2048
#define D_EMB 512
#define H_NUM 8
#define D_HEAD 64
#define NTOK (B_DIM * S_LEN)          // 16384

// ---------------- scratch (static device globals; no runtime alloc) ----------
__device__ float g_q  [(size_t)NTOK * D_EMB];        // 32 MB
__device__ float g_kv [(size_t)NTOK * 2 * D_EMB];    // 64 MB
__device__ float g_att[(size_t)NTOK * D_EMB];        // 32 MB
__device__ float g_y  [(size_t)NTOK * D_EMB];        // 32 MB
__device__ float g_maskf[B_DIM * S_LEN];             // 64 KB

// ---------------- mask dtype detection + expansion ---------------------------
__global__ void mask_expand_kernel(const void* __restrict__ mraw,
                                   float* __restrict__ mf)
{
    const int tid = threadIdx.x;
    const unsigned int* w = (const unsigned int*)mraw;
    int lf_u8 = 0, lf_i32 = 0, lf_f32 = 0, lf_b16 = 0;
    for (int i = tid; i < 4096; i += 256) {
        unsigned int x = w[i];
        if (x == 0u) continue;
        if (x == 0x3F800000u) { lf_f32 = 1; continue; }          // fp32 1.0
        if (x == 0x00003F80u || x == 0x3F803F80u) { lf_b16 = 1; continue; }
        if (x == 1u) { lf_i32 = 1; continue; }
        bool u8ok = true;
        #pragma unroll
        for (int s = 0; s < 32; s += 8) {
            unsigned int byte = (x >> s) & 0xFFu;
            if (byte > 1u) u8ok = false;
        }
        if (u8ok) lf_u8 = 1;
    }
    int any_b16 = __syncthreads_or(lf_b16);
    int any_f32 = __syncthreads_or(lf_f32);
    int any_u8  = __syncthreads_or(lf_u8);
    int any_i32 = __syncthreads_or(lf_i32);

    int mode;                 // 0=u8, 1=i32, 2=f32, 3=bf16
    if (any_b16)      mode = 3;
    else if (any_f32) mode = 2;
    else if (any_u8)  mode = 0;
    else if (any_i32) mode = 1;
    else              mode = 0;

    for (int j = tid; j < B_DIM * S_LEN; j += 256) {
        bool m;
        if (mode == 0)      m = ((const unsigned char*) mraw)[j] != 0;
        else if (mode == 1) m = ((const int*)           mraw)[j] != 0;
        else if (mode == 2) m = ((const float*)         mraw)[j] != 0.0f;
        else                m = ((const unsigned short*)mraw)[j] != 0;
        mf[j] = m ? 1.0f : 0.0f;
    }
}

// ---------------- fp32 SGEMM: C[M,N] = A[M,K] @ W[K,N] (+bias)(+residual) ----
__global__ __launch_bounds__(256)
void sgemm_kernel(const float* __restrict__ A, const float* __restrict__ W,
                  float* __restrict__ C, int M, int N, int K,
                  const float* __restrict__ bias,
                  const float* __restrict__ residual)
{
    __shared__ float As[16][132];   // As[k][m]
    __shared__ float Ws[16][132];   // Ws[k][n]

    const int tid = threadIdx.x;
    const int m0 = blockIdx.y * 128;
    const int n0 = blockIdx.x * 128;
    const int ty = tid >> 4, tx = tid & 15;

    float acc[8][8];
    #pragma unroll
    for (int i = 0; i < 8; i++)
        #pragma unroll
        for (int j = 0; j < 8; j++) acc[i][j] = 0.0f;

    const int alr = tid >> 2;
    const int alc = (tid & 3) << 2;
    const int wlr = tid >> 5;
    const int wlc = (tid & 31) << 2;

    for (int kb = 0; kb < K; kb += 16) {
        #pragma unroll
        for (int p = 0; p < 2; p++) {
            float4 a = *(const float4*)(A + (size_t)(m0 + alr + p * 64) * K + kb + alc);
            As[alc + 0][alr + p * 64] = a.x;
            As[alc + 1][alr + p * 64] = a.y;
            As[alc + 2][alr + p * 64] = a.z;
            As[alc + 3][alr + p * 64] = a.w;
            float4 wv = *(const float4*)(W + (size_t)(kb + wlr + p * 8) * N + n0 + wlc);
            *(float4*)&Ws[wlr + p * 8][wlc] = wv;
        }
        __syncthreads();
        #pragma unroll
        for (int kk = 0; kk < 16; kk++) {
            float af[8], wf[8];
            *(float4*)(af + 0) = *(const float4*)&As[kk][ty * 8 + 0];
            *(float4*)(af + 4) = *(const float4*)&As[kk][ty * 8 + 4];
            *(float4*)(wf + 0) = *(const float4*)&Ws[kk][tx * 8 + 0];
            *(float4*)(wf + 4) = *(const float4*)&Ws[kk][tx * 8 + 4];
            #pragma unroll
            for (int i = 0; i < 8; i++)
                #pragma unroll
                for (int j = 0; j < 8; j++)
                    acc[i][j] = fmaf(af[i], wf[j], acc[i][j]);
        }
        __syncthreads();
    }

    #pragma unroll
    for (int i = 0; i < 8; i++) {
        const int row = m0 + ty * 8 + i;
        #pragma unroll
        for (int j4 = 0; j4 < 8; j4 += 4) {
            const int col = n0 + tx * 8 + j4;
            float4 c = make_float4(acc[i][j4 + 0], acc[i][j4 + 1],
                                   acc[i][j4 + 2], acc[i][j4 + 3]);
            if (bias) {
                float4 bb = *(const float4*)(bias + col);
                c.x += bb.x; c.y += bb.y; c.z += bb.z; c.w += bb.w;
            }
            if (residual) {
                float4 r = *(const float4*)(residual + (size_t)row * N + col);
                c.x += r.x; c.y += r.y; c.z += r.z; c.w += r.w;
            }
            *(float4*)(C + (size_t)row * N + col) = c;
        }
    }
}

// ---------------- tensor-core helpers ----------------------------------------
__device__ __forceinline__ unsigned sptr(const void* p) {
    return (unsigned)__cvta_generic_to_shared(p);
}
__device__ __forceinline__ unsigned pack2bf(float x, float y) {
    unsigned lo = (unsigned)__bfloat16_as_ushort(__float2bfloat16_rn(x));
    unsigned hi = (unsigned)__bfloat16_as_ushort(__float2bfloat16_rn(y));
    return lo | (hi << 16);
}
// split (x,y) into bf16 hi pair + bf16 residual-lo pair
__device__ __forceinline__ void split2(float x, float y, unsigned& h, unsigned& l) {
    __nv_bfloat16 bx = __float2bfloat16_rn(x);
    __nv_bfloat16 by = __float2bfloat16_rn(y);
    h = (unsigned)__bfloat16_as_ushort(bx) | ((unsigned)__bfloat16_as_ushort(by) << 16);
    l = pack2bf(x - __bfloat162float(bx), y - __bfloat162float(by));
}
__device__ __forceinline__ void ldmx2(unsigned& r0, unsigned& r1, unsigned a) {
    asm volatile("ldmatrix.sync.aligned.m8n8.x2.shared.b16 {%0,%1}, [%2];"
                 : "=r"(r0), "=r"(r1) : "r"(a));
}
__device__ __forceinline__ void ldmx2t(unsigned& r0, unsigned& r1, unsigned a) {
    asm volatile("ldmatrix.sync.aligned.m8n8.x2.trans.shared.b16 {%0,%1}, [%2];"
                 : "=r"(r0), "=r"(r1) : "r"(a));
}
__device__ __forceinline__ void mma16816(float* d, const unsigned* a,
                                         unsigned b0, unsigned b1) {
    asm volatile(
        "mma.sync.aligned.m16n8k16.row.col.f32.bf16.bf16.f32 "
        "{%0,%1,%2,%3},{%4,%5,%6,%7},{%8,%9},{%0,%1,%2,%3};"
        : "+f"(d[0]), "+f"(d[1]), "+f"(d[2]), "+f"(d[3])
        : "r"(a[0]), "r"(a[1]), "r"(a[2]), "r"(a[3]), "r"(b0), "r"(b1));
}

// ---------------- flash attention: mma.sync bf16 hi/lo split -----------------
// 256 threads = 8 warps. Tile 128q x 128k. Warp w owns q rows [16w,16w+16).
// K,V staged in smem bf16 hi/lo [128][72]; Q frags + softmax + P all in regs.
#define KSTR 72
#define ATTN_SMEM (4 * 128 * KSTR * 2)    // 73728 B

__global__ __launch_bounds__(256)
void attn_kernel(const float* __restrict__ bias,
                 const float* __restrict__ gamma_f)
{
    extern __shared__ __nv_bfloat16 smem_bf[];
    __nv_bfloat16* Kh = smem_bf;
    __nv_bfloat16* Kl = Kh + 128 * KSTR;
    __nv_bfloat16* Vh = Kl + 128 * KSTR;
    __nv_bfloat16* Vl = Vh + 128 * KSTR;

    const int tid  = threadIdx.x;
    const int w    = tid >> 5;
    const int lane = tid & 31;
    const int g    = lane >> 2, tc = lane & 3;
    const int qt = blockIdx.x, h = blockIdx.y, b = blockIdx.z;
    const float gam = gamma_f[h];
    const int nq0 = b * S_LEN + qt * 128;
    const int qr  = w * 16 + g;              // local q row (row g); +8 = second

    // ---- Q fragments straight from gmem (scaled by 0.125, split hi/lo) ----
    unsigned aqh[4][4], aql[4][4];
    {
        const float* qb = g_q + (size_t)(nq0 + qr) * D_EMB + h * D_HEAD;
        #pragma unroll
        for (int ks = 0; ks < 4; ks++) {
            const float* p0 = qb + ks * 16 + 2 * tc;
            float2 f0 = *(const float2*)(p0);
            float2 f1 = *(const float2*)(p0 + 8 * D_EMB);
            float2 f2 = *(const float2*)(p0 + 8);
            float2 f3 = *(const float2*)(p0 + 8 * D_EMB + 8);
            split2(f0.x * 0.125f, f0.y * 0.125f, aqh[ks][0], aql[ks][0]);
            split2(f1.x * 0.125f, f1.y * 0.125f, aqh[ks][1], aql[ks][1]);
            split2(f2.x * 0.125f, f2.y * 0.125f, aqh[ks][2], aql[ks][2]);
            split2(f3.x * 0.125f, f3.y * 0.125f, aqh[ks][3], aql[ks][3]);
        }
    }

    float oacc[8][4];
    #pragma unroll
    for (int i = 0; i < 8; i++) { oacc[i][0]=0; oacc[i][1]=0; oacc[i][2]=0; oacc[i][3]=0; }
    float m_g = -1e30f, m_g8 = -1e30f, l_g = 0.0f, l_g8 = 0.0f;

    const int ty = tid >> 4, tx = tid & 15, c4 = tx << 2;
    const int lr7 = lane & 7, lsel = (lane >> 3) & 1, lr15 = lane & 15;

    for (int kt = 0; kt < S_LEN / 128; kt++) {
        __syncthreads();
        // ---- stage K,V as bf16 hi/lo ----
        #pragma unroll
        for (int p = 0; p < 8; p++) {
            const int row = ty + p * 16;
            const size_t nk = (size_t)(b * S_LEN + kt * 128 + row);
            float4 kv = *(const float4*)(g_kv + nk * (2 * D_EMB) + h * D_HEAD + c4);
            unsigned h0, l0, h1, l1;
            split2(kv.x, kv.y, h0, l0); split2(kv.z, kv.w, h1, l1);
            *(unsigned*)&Kh[row * KSTR + c4]     = h0;
            *(unsigned*)&Kh[row * KSTR + c4 + 2] = h1;
            *(unsigned*)&Kl[row * KSTR + c4]     = l0;
            *(unsigned*)&Kl[row * KSTR + c4 + 2] = l1;
            float4 vv = *(const float4*)(g_kv + nk * (2 * D_EMB) + D_EMB + h * D_HEAD + c4);
            split2(vv.x, vv.y, h0, l0); split2(vv.z, vv.w, h1, l1);
            *(unsigned*)&Vh[row * KSTR + c4]     = h0;
            *(unsigned*)&Vh[row * KSTR + c4 + 2] = h1;
            *(unsigned*)&Vl[row * KSTR + c4]     = l0;
            *(unsigned*)&Vl[row * KSTR + c4 + 2] = l1;
        }
        __syncthreads();

        // ---- S = Q K^T via mma (hi*hi + hi*lo + lo*hi) ----
        float sacc[16][4];
        #pragma unroll
        for (int nt = 0; nt < 16; nt++) {
            sacc[nt][0]=0; sacc[nt][1]=0; sacc[nt][2]=0; sacc[nt][3]=0;
        }
        #pragma unroll
        for (int nt = 0; nt < 16; nt++) {
            #pragma unroll
            for (int ks = 0; ks < 4; ks++) {
                const int off = (nt * 8 + lr7) * KSTR + ks * 16 + 8 * lsel;
                unsigned bh0, bh1, bl0, bl1;
                ldmx2(bh0, bh1, sptr(&Kh[off]));
                ldmx2(bl0, bl1, sptr(&Kl[off]));
                mma16816(sacc[nt], aqh[ks], bh0, bh1);
                mma16816(sacc[nt], aqh[ks], bl0, bl1);
                mma16816(sacc[nt], aql[ks], bh0, bh1);
            }
        }

        // ---- gamma*bias + mask (register-resident) ----
        const int ql0 = qt * 128 + w * 16 + g;
        const float* brow0 = bias + ((size_t)b * S_LEN + ql0) * S_LEN + kt * 128;
        const float* brow8 = brow0 + (size_t)8 * S_LEN;
        const float* mrow  = g_maskf + b * S_LEN + kt * 128;
        #pragma unroll
        for (int nt = 0; nt < 16; nt++) {
            const int col = nt * 8 + 2 * tc;
            float2 mk = *(const float2*)(mrow + col);
            float2 b0 = *(const float2*)(brow0 + col);
            float2 b8 = *(const float2*)(brow8 + col);
            sacc[nt][0] = (mk.x != 0.0f) ? -1e9f : fmaf(gam, b0.x, sacc[nt][0]);
            sacc[nt][1] = (mk.y != 0.0f) ? -1e9f : fmaf(gam, b0.y, sacc[nt][1]);
            sacc[nt][2] = (mk.x != 0.0f) ? -1e9f : fmaf(gam, b8.x, sacc[nt][2]);
            sacc[nt][3] = (mk.y != 0.0f) ? -1e9f : fmaf(gam, b8.y, sacc[nt][3]);
        }

        // ---- online softmax in registers (quad shfl over lanes tc) ----
        float t0 = -1e30f, t8 = -1e30f;
        #pragma unroll
        for (int nt = 0; nt < 16; nt++) {
            t0 = fmaxf(t0, fmaxf(sacc[nt][0], sacc[nt][1]));
            t8 = fmaxf(t8, fmaxf(sacc[nt][2], sacc[nt][3]));
        }
        t0 = fmaxf(t0, __shfl_xor_sync(0xffffffffu, t0, 1));
        t0 = fmaxf(t0, __shfl_xor_sync(0xffffffffu, t0, 2));
        t8 = fmaxf(t8, __shfl_xor_sync(0xffffffffu, t8, 1));
        t8 = fmaxf(t8, __shfl_xor_sync(0xffffffffu, t8, 2));
        const float mn0 = fmaxf(m_g, t0), mn8 = fmaxf(m_g8, t8);
        const float cor0 = __expf(m_g - mn0), cor8 = __expf(m_g8 - mn8);
        m_g = mn0; m_g8 = mn8;

        float ps0 = 0.0f, ps8 = 0.0f;
        unsigned phx[16], plx[16], phz[16], plz[16];
        #pragma unroll
        for (int nt = 0; nt < 16; nt++) {
            float e0 = __expf(sacc[nt][0] - mn0);
            float e1 = __expf(sacc[nt][1] - mn0);
            float e2 = __expf(sacc[nt][2] - mn8);
            float e3 = __expf(sacc[nt][3] - mn8);
            ps0 += e0 + e1; ps8 += e2 + e3;
            split2(e0, e1, phx[nt], plx[nt]);
            split2(e2, e3, phz[nt], plz[nt]);
        }
        ps0 += __shfl_xor_sync(0xffffffffu, ps0, 1);
        ps0 += __shfl_xor_sync(0xffffffffu, ps0, 2);
        ps8 += __shfl_xor_sync(0xffffffffu, ps8, 1);
        ps8 += __shfl_xor_sync(0xffffffffu, ps8, 2);
        l_g  = l_g  * cor0 + ps0;
        l_g8 = l_g8 * cor8 + ps8;

        #pragma unroll
        for (int i = 0; i < 8; i++) {
            oacc[i][0] *= cor0; oacc[i][1] *= cor0;
            oacc[i][2] *= cor8; oacc[i][3] *= cor8;
        }

        // ---- O += P @ V : P frags are the softmax registers (exact layout) ----
        #pragma unroll
        for (int nt2 = 0; nt2 < 8; nt2++) {
            #pragma unroll
            for (int kp = 0; kp < 8; kp++) {
                const unsigned ap[4] = { phx[2*kp], phz[2*kp], phx[2*kp+1], phz[2*kp+1] };
                const unsigned al[4] = { plx[2*kp], plz[2*kp], plx[2*kp+1], plz[2*kp+1] };
                const int off = (kp * 16 + lr15) * KSTR + nt2 * 8;
                unsigned bh0, bh1, bl0, bl1;
                ldmx2t(bh0, bh1, sptr(&Vh[off]));
                ldmx2t(bl0, bl1, sptr(&Vl[off]));
                mma16816(oacc[nt2], ap, bh0, bh1);
                mma16816(oacc[nt2], ap, bl0, bl1);
                mma16816(oacc[nt2], al, bh0, bh1);
            }
        }
    }

    // ---- epilogue: normalize and store ----
    const float inv0 = 1.0f / l_g, inv8 = 1.0f / l_g8;
    float* ob = g_att + (size_t)(nq0 + qr) * D_EMB + h * D_HEAD;
    #pragma unroll
    for (int nt2 = 0; nt2 < 8; nt2++) {
        const int col = nt2 * 8 + 2 * tc;
        *(float2*)(ob + col) = make_float2(oacc[nt2][0] * inv0, oacc[nt2][1] * inv0);
        *(float2*)(ob + (size_t)8 * D_EMB + col) =
            make_float2(oacc[nt2][2] * inv8, oacc[nt2][3] * inv8);
    }
}

// ---------------- layernorm: one warp per row of 512 -------------------------
__global__ void ln_kernel(const float* __restrict__ y,
                          const float* __restrict__ lng,
                          const float* __restrict__ lnb,
                          float* __restrict__ out)
{
    const int warp = threadIdx.x >> 5, lane = threadIdx.x & 31;
    const int row = blockIdx.x * 8 + warp;
    const float* yr = y + (size_t)row * D_EMB;

    float v[16];
    #pragma unroll
    for (int c = 0; c < 4; c++)
        *(float4*)(v + c * 4) = *(const float4*)(yr + c * 128 + lane * 4);

    float s = 0.0f;
    #pragma unroll
    for (int e = 0; e < 16; e++) s += v[e];
    #pragma unroll
    for (int off = 16; off > 0; off >>= 1) s += __shfl_xor_sync(0xffffffffu, s, off);
    const float mu = s * (1.0f / 512.0f);

    float sq = 0.0f;
    #pragma unroll
    for (int e = 0; e < 16; e++) { const float d = v[e] - mu; sq = fmaf(d, d, sq); }
    #pragma unroll
    for (int off = 16; off > 0; off >>= 1) sq += __shfl_xor_sync(0xffffffffu, sq, off);
    const float rstd = rsqrtf(sq * (1.0f / 512.0f) + 1e-5f);

    #pragma unroll
    for (int c = 0; c < 4; c++) {
        const int col = c * 128 + lane * 4;
        float4 gg = *(const float4*)(lng + col);
        float4 bb = *(const float4*)(lnb + col);
        float4 o;
        o.x = (v[c*4+0] - mu) * rstd * gg.x + bb.x;
        o.y = (v[c*4+1] - mu) * rstd * gg.y + bb.y;
        o.z = (v[c*4+2] - mu) * rstd * gg.z + bb.z;
        o.w = (v[c*4+3] - mu) * rstd * gg.w + bb.w;
        *(float4*)(out + (size_t)row * D_EMB + col) = o;
    }
}

// ---------------- launch ------------------------------------------------------
extern "C" void kernel_launch(void* const* d_in, const int* in_sizes, int n_in,
                              void* d_out, int out_size)
{
    (void)in_sizes; (void)n_in; (void)out_size;
    const float* x_p     = (const float*)d_in[0];
    const float* x_pcre  = (const float*)d_in[1];
    const float* bias    = (const float*)d_in[2];
    const void*  mask    = d_in[3];
    const float* Wq      = (const float*)d_in[4];
    const float* Wkv     = (const float*)d_in[5];
    const float* Wff     = (const float*)d_in[6];
    const float* bff     = (const float*)d_in[7];
    const float* gamma_f = (const float*)d_in[8];
    const float* ln_g    = (const float*)d_in[9];
    const float* ln_b    = (const float*)d_in[10];
    float* out = (float*)d_out;

    float *gq, *gkv, *gatt, *gy, *gmf;
    cudaGetSymbolAddress((void**)&gq,  g_q);
    cudaGetSymbolAddress((void**)&gkv, g_kv);
    cudaGetSymbolAddress((void**)&gatt,g_att);
    cudaGetSymbolAddress((void**)&gy,  g_y);
    cudaGetSymbolAddress((void**)&gmf, g_maskf);

    cudaFuncSetAttribute(attn_kernel, cudaFuncAttributeMaxDynamicSharedMemorySize,
                         ATTN_SMEM);

    mask_expand_kernel<<<1, 256>>>(mask, gmf);
    sgemm_kernel<<<dim3( 4, 128), 256>>>(x_p,    Wq,  gq,  NTOK,  512, 512, nullptr, nullptr);
    sgemm_kernel<<<dim3( 8, 128), 256>>>(x_pcre, Wkv, gkv, NTOK, 1024, 512, nullptr, nullptr);
    attn_kernel<<<dim3(S_LEN / 128, H_NUM, B_DIM), 256, ATTN_SMEM>>>(bias, gamma_f);
    sgemm_kernel<<<dim3( 4, 128), 256>>>(gatt,   Wff, gy,  NTOK,  512, 512, bff, x_p);
    ln_kernel<<<NTOK / 8, 256>>>(gy, ln_g, ln_b, out);
}

// round 10
// speedup vs baseline: 1.5980x; 1.1719x over previous
#include <cuda_runtime.h>
#include <cuda_bf16.h>
#include <cstdint>
#include <cstddef>

#define B_DIM 8
#define S_LEN 2048
#define D_EMB 512
#define H_NUM 8
#define D_HEAD 64
#define NTOK (B_DIM * S_LEN)          // 16384

// ---------------- scratch (static device globals; no runtime alloc) ----------
__device__ float g_q  [(size_t)NTOK * D_EMB];        // 32 MB
__device__ float g_kv [(size_t)NTOK * 2 * D_EMB];    // 64 MB
__device__ float g_att[(size_t)NTOK * D_EMB];        // 32 MB
__device__ float g_y  [(size_t)NTOK * D_EMB];        // 32 MB
__device__ float g_maskf[B_DIM * S_LEN];             // 64 KB

// ---------------- mask dtype detection + expansion ---------------------------
__global__ void mask_expand_kernel(const void* __restrict__ mraw,
                                   float* __restrict__ mf)
{
    const int tid = threadIdx.x;
    const unsigned int* w = (const unsigned int*)mraw;
    int lf_u8 = 0, lf_i32 = 0, lf_f32 = 0, lf_b16 = 0;
    for (int i = tid; i < 4096; i += 256) {
        unsigned int x = w[i];
        if (x == 0u) continue;
        if (x == 0x3F800000u) { lf_f32 = 1; continue; }          // fp32 1.0
        if (x == 0x00003F80u || x == 0x3F803F80u) { lf_b16 = 1; continue; }
        if (x == 1u) { lf_i32 = 1; continue; }
        bool u8ok = true;
        #pragma unroll
        for (int s = 0; s < 32; s += 8) {
            unsigned int byte = (x >> s) & 0xFFu;
            if (byte > 1u) u8ok = false;
        }
        if (u8ok) lf_u8 = 1;
    }
    int any_b16 = __syncthreads_or(lf_b16);
    int any_f32 = __syncthreads_or(lf_f32);
    int any_u8  = __syncthreads_or(lf_u8);
    int any_i32 = __syncthreads_or(lf_i32);

    int mode;                 // 0=u8, 1=i32, 2=f32, 3=bf16
    if (any_b16)      mode = 3;
    else if (any_f32) mode = 2;
    else if (any_u8)  mode = 0;
    else if (any_i32) mode = 1;
    else              mode = 0;

    for (int j = tid; j < B_DIM * S_LEN; j += 256) {
        bool m;
        if (mode == 0)      m = ((const unsigned char*) mraw)[j] != 0;
        else if (mode == 1) m = ((const int*)           mraw)[j] != 0;
        else if (mode == 2) m = ((const float*)         mraw)[j] != 0.0f;
        else                m = ((const unsigned short*)mraw)[j] != 0;
        mf[j] = m ? 1.0f : 0.0f;
    }
}

// ---------------- tensor-core helpers ----------------------------------------
__device__ __forceinline__ unsigned sptr(const void* p) {
    return (unsigned)__cvta_generic_to_shared(p);
}
__device__ __forceinline__ unsigned pack2bf(float x, float y) {
    unsigned lo = (unsigned)__bfloat16_as_ushort(__float2bfloat16_rn(x));
    unsigned hi = (unsigned)__bfloat16_as_ushort(__float2bfloat16_rn(y));
    return lo | (hi << 16);
}
// split (x,y) into bf16 hi pair + bf16 residual-lo pair
__device__ __forceinline__ void split2(float x, float y, unsigned& h, unsigned& l) {
    __nv_bfloat16 bx = __float2bfloat16_rn(x);
    __nv_bfloat16 by = __float2bfloat16_rn(y);
    h = (unsigned)__bfloat16_as_ushort(bx) | ((unsigned)__bfloat16_as_ushort(by) << 16);
    l = pack2bf(x - __bfloat162float(bx), y - __bfloat162float(by));
}
__device__ __forceinline__ void ldmx2(unsigned& r0, unsigned& r1, unsigned a) {
    asm volatile("ldmatrix.sync.aligned.m8n8.x2.shared.b16 {%0,%1}, [%2];"
                 : "=r"(r0), "=r"(r1) : "r"(a));
}
__device__ __forceinline__ void ldmx2t(unsigned& r0, unsigned& r1, unsigned a) {
    asm volatile("ldmatrix.sync.aligned.m8n8.x2.trans.shared.b16 {%0,%1}, [%2];"
                 : "=r"(r0), "=r"(r1) : "r"(a));
}
__device__ __forceinline__ void ldmx4(unsigned* r, unsigned a) {
    asm volatile("ldmatrix.sync.aligned.m8n8.x4.shared.b16 {%0,%1,%2,%3}, [%4];"
                 : "=r"(r[0]), "=r"(r[1]), "=r"(r[2]), "=r"(r[3]) : "r"(a));
}
__device__ __forceinline__ void mma16816(float* d, const unsigned* a,
                                         unsigned b0, unsigned b1) {
    asm volatile(
        "mma.sync.aligned.m16n8k16.row.col.f32.bf16.bf16.f32 "
        "{%0,%1,%2,%3},{%4,%5,%6,%7},{%8,%9},{%0,%1,%2,%3};"
        : "+f"(d[0]), "+f"(d[1]), "+f"(d[2]), "+f"(d[3])
        : "r"(a[0]), "r"(a[1]), "r"(a[2]), "r"(a[3]), "r"(b0), "r"(b1));
}

// ---------------- tensor-core GEMM (bf16 hi/lo split, fp32 accumulate) -------
// C[M,N] = A[M,K] @ W[K,N] (+bias)(+residual).  128x128 CTA tile, BK=64.
// 8 warps in 2(m) x 4(n); warp tile 64x32 via m16n8k16 (4 m-frags x 4 n-frags).
#define ASTR 72
#define WSTR 136
#define GEMM_SMEM ((2 * 128 * ASTR + 2 * 64 * WSTR) * 2)   // 71680 B

__global__ __launch_bounds__(256)
void tgemm_kernel(const float* __restrict__ A, const float* __restrict__ W,
                  float* __restrict__ C, int M, int N, int K,
                  const float* __restrict__ bias,
                  const float* __restrict__ residual)
{
    extern __shared__ __nv_bfloat16 sg[];
    __nv_bfloat16* Ah = sg;
    __nv_bfloat16* Al = Ah + 128 * ASTR;
    __nv_bfloat16* Wh = Al + 128 * ASTR;
    __nv_bfloat16* Wl = Wh + 64 * WSTR;

    const int tid = threadIdx.x;
    const int w = tid >> 5, lane = tid & 31;
    const int wm = w >> 2, wn = w & 3;
    const int m0 = blockIdx.y * 128, n0 = blockIdx.x * 128;
    const int g = lane >> 2, tc = lane & 3;
    const int lr15 = lane & 15;

    float acc[4][4][4];
    #pragma unroll
    for (int mt = 0; mt < 4; mt++)
        #pragma unroll
        for (int nt = 0; nt < 4; nt++) {
            acc[mt][nt][0] = 0.0f; acc[mt][nt][1] = 0.0f;
            acc[mt][nt][2] = 0.0f; acc[mt][nt][3] = 0.0f;
        }

    const int ar  = tid >> 4, ac4 = (tid & 15) << 2;   // A stage: 16 rows x 64 cols
    const int wr  = tid >> 5, wc4 = (tid & 31) << 2;   // W stage: 8 rows x 128 cols

    for (int kb = 0; kb < K; kb += 64) {
        __syncthreads();
        // ---- stage A[128][64] as bf16 hi/lo ----
        #pragma unroll
        for (int p = 0; p < 8; p++) {
            const int row = ar + p * 16;
            float4 a = *(const float4*)(A + (size_t)(m0 + row) * K + kb + ac4);
            unsigned h0, l0, h1, l1;
            split2(a.x, a.y, h0, l0); split2(a.z, a.w, h1, l1);
            *(unsigned*)&Ah[row * ASTR + ac4]     = h0;
            *(unsigned*)&Ah[row * ASTR + ac4 + 2] = h1;
            *(unsigned*)&Al[row * ASTR + ac4]     = l0;
            *(unsigned*)&Al[row * ASTR + ac4 + 2] = l1;
        }
        // ---- stage W[64][128] as bf16 hi/lo ----
        #pragma unroll
        for (int p = 0; p < 8; p++) {
            const int row = wr + p * 8;
            float4 v = *(const float4*)(W + (size_t)(kb + row) * N + n0 + wc4);
            unsigned h0, l0, h1, l1;
            split2(v.x, v.y, h0, l0); split2(v.z, v.w, h1, l1);
            *(unsigned*)&Wh[row * WSTR + wc4]     = h0;
            *(unsigned*)&Wh[row * WSTR + wc4 + 2] = h1;
            *(unsigned*)&Wl[row * WSTR + wc4]     = l0;
            *(unsigned*)&Wl[row * WSTR + wc4 + 2] = l1;
        }
        __syncthreads();

        #pragma unroll
        for (int ks = 0; ks < 4; ks++) {
            // B-fragments for this warp's 4 n-tiles (hi + lo)
            unsigned bh[4][2], bl[4][2];
            #pragma unroll
            for (int nt = 0; nt < 4; nt++) {
                const int off = (ks * 16 + lr15) * WSTR + wn * 32 + nt * 8;
                ldmx2t(bh[nt][0], bh[nt][1], sptr(&Wh[off]));
                ldmx2t(bl[nt][0], bl[nt][1], sptr(&Wl[off]));
            }
            #pragma unroll
            for (int mt = 0; mt < 4; mt++) {
                unsigned ahf[4], alf[4];
                const int aoff = (wm * 64 + mt * 16 + lr15) * ASTR
                               + ks * 16 + 8 * (lane >> 4);
                ldmx4(ahf, sptr(&Ah[aoff]));
                ldmx4(alf, sptr(&Al[aoff]));
                #pragma unroll
                for (int nt = 0; nt < 4; nt++) {
                    mma16816(acc[mt][nt], ahf, bh[nt][0], bh[nt][1]);
                    mma16816(acc[mt][nt], ahf, bl[nt][0], bl[nt][1]);
                    mma16816(acc[mt][nt], alf, bh[nt][0], bh[nt][1]);
                }
            }
        }
    }

    // ---- epilogue: bias + residual, fp32 store ----
    #pragma unroll
    for (int mt = 0; mt < 4; mt++) {
        const int row0 = m0 + wm * 64 + mt * 16 + g;
        #pragma unroll
        for (int nt = 0; nt < 4; nt++) {
            const int col = n0 + wn * 32 + nt * 8 + 2 * tc;
            float2 c0 = make_float2(acc[mt][nt][0], acc[mt][nt][1]);
            float2 c1 = make_float2(acc[mt][nt][2], acc[mt][nt][3]);
            if (bias) {
                float2 bb = *(const float2*)(bias + col);
                c0.x += bb.x; c0.y += bb.y; c1.x += bb.x; c1.y += bb.y;
            }
            if (residual) {
                float2 r0 = *(const float2*)(residual + (size_t)row0 * N + col);
                float2 r1 = *(const float2*)(residual + (size_t)(row0 + 8) * N + col);
                c0.x += r0.x; c0.y += r0.y; c1.x += r1.x; c1.y += r1.y;
            }
            *(float2*)(C + (size_t)row0 * N + col) = c0;
            *(float2*)(C + (size_t)(row0 + 8) * N + col) = c1;
        }
    }
}

// ---------------- flash attention: mma.sync bf16 hi/lo split -----------------
// 256 threads = 8 warps. Tile 128q x 128k. Warp w owns q rows [16w,16w+16).
#define KSTR 72
#define ATTN_SMEM (4 * 128 * KSTR * 2)    // 73728 B

__global__ __launch_bounds__(256)
void attn_kernel(const float* __restrict__ bias,
                 const float* __restrict__ gamma_f)
{
    extern __shared__ __nv_bfloat16 smem_bf[];
    __nv_bfloat16* Kh = smem_bf;
    __nv_bfloat16* Kl = Kh + 128 * KSTR;
    __nv_bfloat16* Vh = Kl + 128 * KSTR;
    __nv_bfloat16* Vl = Vh + 128 * KSTR;

    const int tid  = threadIdx.x;
    const int w    = tid >> 5;
    const int lane = tid & 31;
    const int g    = lane >> 2, tc = lane & 3;
    const int qt = blockIdx.x, h = blockIdx.y, b = blockIdx.z;
    const float gam = gamma_f[h];
    const int nq0 = b * S_LEN + qt * 128;
    const int qr  = w * 16 + g;

    // ---- Q fragments straight from gmem (scaled by 0.125, split hi/lo) ----
    unsigned aqh[4][4], aql[4][4];
    {
        const float* qb = g_q + (size_t)(nq0 + qr) * D_EMB + h * D_HEAD;
        #pragma unroll
        for (int ks = 0; ks < 4; ks++) {
            const float* p0 = qb + ks * 16 + 2 * tc;
            float2 f0 = *(const float2*)(p0);
            float2 f1 = *(const float2*)(p0 + 8 * D_EMB);
            float2 f2 = *(const float2*)(p0 + 8);
            float2 f3 = *(const float2*)(p0 + 8 * D_EMB + 8);
            split2(f0.x * 0.125f, f0.y * 0.125f, aqh[ks][0], aql[ks][0]);
            split2(f1.x * 0.125f, f1.y * 0.125f, aqh[ks][1], aql[ks][1]);
            split2(f2.x * 0.125f, f2.y * 0.125f, aqh[ks][2], aql[ks][2]);
            split2(f3.x * 0.125f, f3.y * 0.125f, aqh[ks][3], aql[ks][3]);
        }
    }

    float oacc[8][4];
    #pragma unroll
    for (int i = 0; i < 8; i++) { oacc[i][0]=0; oacc[i][1]=0; oacc[i][2]=0; oacc[i][3]=0; }
    float m_g = -1e30f, m_g8 = -1e30f, l_g = 0.0f, l_g8 = 0.0f;

    const int ty = tid >> 4, tx = tid & 15, c4 = tx << 2;
    const int lr7 = lane & 7, lsel = (lane >> 3) & 1, lr15 = lane & 15;

    for (int kt = 0; kt < S_LEN / 128; kt++) {
        __syncthreads();
        // ---- stage K,V as bf16 hi/lo ----
        #pragma unroll
        for (int p = 0; p < 8; p++) {
            const int row = ty + p * 16;
            const size_t nk = (size_t)(b * S_LEN + kt * 128 + row);
            float4 kv = *(const float4*)(g_kv + nk * (2 * D_EMB) + h * D_HEAD + c4);
            unsigned h0, l0, h1, l1;
            split2(kv.x, kv.y, h0, l0); split2(kv.z, kv.w, h1, l1);
            *(unsigned*)&Kh[row * KSTR + c4]     = h0;
            *(unsigned*)&Kh[row * KSTR + c4 + 2] = h1;
            *(unsigned*)&Kl[row * KSTR + c4]     = l0;
            *(unsigned*)&Kl[row * KSTR + c4 + 2] = l1;
            float4 vv = *(const float4*)(g_kv + nk * (2 * D_EMB) + D_EMB + h * D_HEAD + c4);
            split2(vv.x, vv.y, h0, l0); split2(vv.z, vv.w, h1, l1);
            *(unsigned*)&Vh[row * KSTR + c4]     = h0;
            *(unsigned*)&Vh[row * KSTR + c4 + 2] = h1;
            *(unsigned*)&Vl[row * KSTR + c4]     = l0;
            *(unsigned*)&Vl[row * KSTR + c4 + 2] = l1;
        }
        __syncthreads();

        // ---- S = Q K^T via mma (hi*hi + hi*lo + lo*hi) ----
        float sacc[16][4];
        #pragma unroll
        for (int nt = 0; nt < 16; nt++) {
            sacc[nt][0]=0; sacc[nt][1]=0; sacc[nt][2]=0; sacc[nt][3]=0;
        }
        #pragma unroll
        for (int nt = 0; nt < 16; nt++) {
            #pragma unroll
            for (int ks = 0; ks < 4; ks++) {
                const int off = (nt * 8 + lr7) * KSTR + ks * 16 + 8 * lsel;
                unsigned bh0, bh1, bl0, bl1;
                ldmx2(bh0, bh1, sptr(&Kh[off]));
                ldmx2(bl0, bl1, sptr(&Kl[off]));
                mma16816(sacc[nt], aqh[ks], bh0, bh1);
                mma16816(sacc[nt], aqh[ks], bl0, bl1);
                mma16816(sacc[nt], aql[ks], bh0, bh1);
            }
        }

        // ---- gamma*bias + mask (register-resident) ----
        const int ql0 = qt * 128 + w * 16 + g;
        const float* brow0 = bias + ((size_t)b * S_LEN + ql0) * S_LEN + kt * 128;
        const float* brow8 = brow0 + (size_t)8 * S_LEN;
        const float* mrow  = g_maskf + b * S_LEN + kt * 128;
        #pragma unroll
        for (int nt = 0; nt < 16; nt++) {
            const int col = nt * 8 + 2 * tc;
            float2 mk = *(const float2*)(mrow + col);
            float2 b0 = *(const float2*)(brow0 + col);
            float2 b8 = *(const float2*)(brow8 + col);
            sacc[nt][0] = (mk.x != 0.0f) ? -1e9f : fmaf(gam, b0.x, sacc[nt][0]);
            sacc[nt][1] = (mk.y != 0.0f) ? -1e9f : fmaf(gam, b0.y, sacc[nt][1]);
            sacc[nt][2] = (mk.x != 0.0f) ? -1e9f : fmaf(gam, b8.x, sacc[nt][2]);
            sacc[nt][3] = (mk.y != 0.0f) ? -1e9f : fmaf(gam, b8.y, sacc[nt][3]);
        }

        // ---- online softmax in registers (quad shfl) ----
        float t0 = -1e30f, t8 = -1e30f;
        #pragma unroll
        for (int nt = 0; nt < 16; nt++) {
            t0 = fmaxf(t0, fmaxf(sacc[nt][0], sacc[nt][1]));
            t8 = fmaxf(t8, fmaxf(sacc[nt][2], sacc[nt][3]));
        }
        t0 = fmaxf(t0, __shfl_xor_sync(0xffffffffu, t0, 1));
        t0 = fmaxf(t0, __shfl_xor_sync(0xffffffffu, t0, 2));
        t8 = fmaxf(t8, __shfl_xor_sync(0xffffffffu, t8, 1));
        t8 = fmaxf(t8, __shfl_xor_sync(0xffffffffu, t8, 2));
        const float mn0 = fmaxf(m_g, t0), mn8 = fmaxf(m_g8, t8);
        const float cor0 = __expf(m_g - mn0), cor8 = __expf(m_g8 - mn8);
        m_g = mn0; m_g8 = mn8;

        float ps0 = 0.0f, ps8 = 0.0f;
        unsigned phx[16], plx[16], phz[16], plz[16];
        #pragma unroll
        for (int nt = 0; nt < 16; nt++) {
            float e0 = __expf(sacc[nt][0] - mn0);
            float e1 = __expf(sacc[nt][1] - mn0);
            float e2 = __expf(sacc[nt][2] - mn8);
            float e3 = __expf(sacc[nt][3] - mn8);
            ps0 += e0 + e1; ps8 += e2 + e3;
            split2(e0, e1, phx[nt], plx[nt]);
            split2(e2, e3, phz[nt], plz[nt]);
        }
        ps0 += __shfl_xor_sync(0xffffffffu, ps0, 1);
        ps0 += __shfl_xor_sync(0xffffffffu, ps0, 2);
        ps8 += __shfl_xor_sync(0xffffffffu, ps8, 1);
        ps8 += __shfl_xor_sync(0xffffffffu, ps8, 2);
        l_g  = l_g  * cor0 + ps0;
        l_g8 = l_g8 * cor8 + ps8;

        #pragma unroll
        for (int i = 0; i < 8; i++) {
            oacc[i][0] *= cor0; oacc[i][1] *= cor0;
            oacc[i][2] *= cor8; oacc[i][3] *= cor8;
        }

        // ---- O += P @ V ----
        #pragma unroll
        for (int nt2 = 0; nt2 < 8; nt2++) {
            #pragma unroll
            for (int kp = 0; kp < 8; kp++) {
                const unsigned ap[4] = { phx[2*kp], phz[2*kp], phx[2*kp+1], phz[2*kp+1] };
                const unsigned al[4] = { plx[2*kp], plz[2*kp], plx[2*kp+1], plz[2*kp+1] };
                const int off = (kp * 16 + lr15) * KSTR + nt2 * 8;
                unsigned bh0, bh1, bl0, bl1;
                ldmx2t(bh0, bh1, sptr(&Vh[off]));
                ldmx2t(bl0, bl1, sptr(&Vl[off]));
                mma16816(oacc[nt2], ap, bh0, bh1);
                mma16816(oacc[nt2], ap, bl0, bl1);
                mma16816(oacc[nt2], al, bh0, bh1);
            }
        }
    }

    // ---- epilogue: normalize and store ----
    const float inv0 = 1.0f / l_g, inv8 = 1.0f / l_g8;
    float* ob = g_att + (size_t)(nq0 + qr) * D_EMB + h * D_HEAD;
    #pragma unroll
    for (int nt2 = 0; nt2 < 8; nt2++) {
        const int col = nt2 * 8 + 2 * tc;
        *(float2*)(ob + col) = make_float2(oacc[nt2][0] * inv0, oacc[nt2][1] * inv0);
        *(float2*)(ob + (size_t)8 * D_EMB + col) =
            make_float2(oacc[nt2][2] * inv8, oacc[nt2][3] * inv8);
    }
}

// ---------------- layernorm: one warp per row of 512 -------------------------
__global__ void ln_kernel(const float* __restrict__ y,
                          const float* __restrict__ lng,
                          const float* __restrict__ lnb,
                          float* __restrict__ out)
{
    const int warp = threadIdx.x >> 5, lane = threadIdx.x & 31;
    const int row = blockIdx.x * 8 + warp;
    const float* yr = y + (size_t)row * D_EMB;

    float v[16];
    #pragma unroll
    for (int c = 0; c < 4; c++)
        *(float4*)(v + c * 4) = *(const float4*)(yr + c * 128 + lane * 4);

    float s = 0.0f;
    #pragma unroll
    for (int e = 0; e < 16; e++) s += v[e];
    #pragma unroll
    for (int off = 16; off > 0; off >>= 1) s += __shfl_xor_sync(0xffffffffu, s, off);
    const float mu = s * (1.0f / 512.0f);

    float sq = 0.0f;
    #pragma unroll
    for (int e = 0; e < 16; e++) { const float d = v[e] - mu; sq = fmaf(d, d, sq); }
    #pragma unroll
    for (int off = 16; off > 0; off >>= 1) sq += __shfl_xor_sync(0xffffffffu, sq, off);
    const float rstd = rsqrtf(sq * (1.0f / 512.0f) + 1e-5f);

    #pragma unroll
    for (int c = 0; c < 4; c++) {
        const int col = c * 128 + lane * 4;
        float4 gg = *(const float4*)(lng + col);
        float4 bb = *(const float4*)(lnb + col);
        float4 o;
        o.x = (v[c*4+0] - mu) * rstd * gg.x + bb.x;
        o.y = (v[c*4+1] - mu) * rstd * gg.y + bb.y;
        o.z = (v[c*4+2] - mu) * rstd * gg.z + bb.z;
        o.w = (v[c*4+3] - mu) * rstd * gg.w + bb.w;
        *(float4*)(out + (size_t)row * D_EMB + col) = o;
    }
}

// ---------------- launch ------------------------------------------------------
extern "C" void kernel_launch(void* const* d_in, const int* in_sizes, int n_in,
                              void* d_out, int out_size)
{
    (void)in_sizes; (void)n_in; (void)out_size;
    const float* x_p     = (const float*)d_in[0];
    const float* x_pcre  = (const float*)d_in[1];
    const float* bias    = (const float*)d_in[2];
    const void*  mask    = d_in[3];
    const float* Wq      = (const float*)d_in[4];
    const float* Wkv     = (const float*)d_in[5];
    const float* Wff     = (const float*)d_in[6];
    const float* bff     = (const float*)d_in[7];
    const float* gamma_f = (const float*)d_in[8];
    const float* ln_g    = (const float*)d_in[9];
    const float* ln_b    = (const float*)d_in[10];
    float* out = (float*)d_out;

    float *gq, *gkv, *gatt, *gy, *gmf;
    cudaGetSymbolAddress((void**)&gq,  g_q);
    cudaGetSymbolAddress((void**)&gkv, g_kv);
    cudaGetSymbolAddress((void**)&gatt,g_att);
    cudaGetSymbolAddress((void**)&gy,  g_y);
    cudaGetSymbolAddress((void**)&gmf, g_maskf);

    cudaFuncSetAttribute(attn_kernel, cudaFuncAttributeMaxDynamicSharedMemorySize,
                         ATTN_SMEM);
    cudaFuncSetAttribute(tgemm_kernel, cudaFuncAttributeMaxDynamicSharedMemorySize,
                         GEMM_SMEM);

    mask_expand_kernel<<<1, 256>>>(mask, gmf);
    tgemm_kernel<<<dim3(4, 128), 256, GEMM_SMEM>>>(x_p,    Wq,  gq,  NTOK,  512, 512,
                                                   nullptr, nullptr);
    tgemm_kernel<<<dim3(8, 128), 256, GEMM_SMEM>>>(x_pcre, Wkv, gkv, NTOK, 1024, 512,
                                                   nullptr, nullptr);
    attn_kernel<<<dim3(S_LEN / 128, H_NUM, B_DIM), 256, ATTN_SMEM>>>(bias, gamma_f);
    tgemm_kernel<<<dim3(4, 128), 256, GEMM_SMEM>>>(gatt,   Wff, gy,  NTOK,  512, 512,
                                                   bff, x_p);
    ln_kernel<<<NTOK / 8, 256>>>(gy, ln_g, ln_b, out);
}

// round 13
// speedup vs baseline: 1.7198x; 1.0762x over previous
#include <cuda_runtime.h>
#include <cuda_bf16.h>
#include <cstdint>
#include <cstddef>

#define B_DIM 8
#define S_LEN 2048
#define D_EMB 512
#define H_NUM 8
#define D_HEAD 64
#define NTOK (B_DIM * S_LEN)          // 16384

// ---------------- scratch (static device globals; no runtime alloc) ----------
__device__ float g_q  [(size_t)NTOK * D_EMB];        // 32 MB
__device__ float g_att[(size_t)NTOK * D_EMB];        // 32 MB
__device__ float g_y  [(size_t)NTOK * D_EMB];        // 32 MB
__device__ float g_maskf[B_DIM * S_LEN];             // 64 KB
// pre-split bf16 hi/lo K and V, layout [tok][H*64]
__device__ __nv_bfloat16 g_kh[(size_t)NTOK * 512];   // 16 MB
__device__ __nv_bfloat16 g_kl[(size_t)NTOK * 512];
__device__ __nv_bfloat16 g_vh[(size_t)NTOK * 512];
__device__ __nv_bfloat16 g_vl[(size_t)NTOK * 512];

// ---------------- mask dtype detection + expansion ---------------------------
__global__ void mask_expand_kernel(const void* __restrict__ mraw,
                                   float* __restrict__ mf)
{
    const int tid = threadIdx.x;
    const unsigned int* w = (const unsigned int*)mraw;
    int lf_u8 = 0, lf_i32 = 0, lf_f32 = 0, lf_b16 = 0;
    for (int i = tid; i < 4096; i += 256) {
        unsigned int x = w[i];
        if (x == 0u) continue;
        if (x == 0x3F800000u) { lf_f32 = 1; continue; }          // fp32 1.0
        if (x == 0x00003F80u || x == 0x3F803F80u) { lf_b16 = 1; continue; }
        if (x == 1u) { lf_i32 = 1; continue; }
        bool u8ok = true;
        #pragma unroll
        for (int s = 0; s < 32; s += 8) {
            unsigned int byte = (x >> s) & 0xFFu;
            if (byte > 1u) u8ok = false;
        }
        if (u8ok) lf_u8 = 1;
    }
    int any_b16 = __syncthreads_or(lf_b16);
    int any_f32 = __syncthreads_or(lf_f32);
    int any_u8  = __syncthreads_or(lf_u8);
    int any_i32 = __syncthreads_or(lf_i32);

    int mode;                 // 0=u8, 1=i32, 2=f32, 3=bf16
    if (any_b16)      mode = 3;
    else if (any_f32) mode = 2;
    else if (any_u8)  mode = 0;
    else if (any_i32) mode = 1;
    else              mode = 0;

    for (int j = tid; j < B_DIM * S_LEN; j += 256) {
        bool m;
        if (mode == 0)      m = ((const unsigned char*) mraw)[j] != 0;
        else if (mode == 1) m = ((const int*)           mraw)[j] != 0;
        else if (mode == 2) m = ((const float*)         mraw)[j] != 0.0f;
        else                m = ((const unsigned short*)mraw)[j] != 0;
        mf[j] = m ? 1.0f : 0.0f;
    }
}

// ---------------- tensor-core helpers ----------------------------------------
__device__ __forceinline__ unsigned sptr(const void* p) {
    return (unsigned)__cvta_generic_to_shared(p);
}
__device__ __forceinline__ unsigned pack2bf(float x, float y) {
    unsigned lo = (unsigned)__bfloat16_as_ushort(__float2bfloat16_rn(x));
    unsigned hi = (unsigned)__bfloat16_as_ushort(__float2bfloat16_rn(y));
    return lo | (hi << 16);
}
// split (x,y) into bf16 hi pair + bf16 residual-lo pair
__device__ __forceinline__ void split2(float x, float y, unsigned& h, unsigned& l) {
    __nv_bfloat16 bx = __float2bfloat16_rn(x);
    __nv_bfloat16 by = __float2bfloat16_rn(y);
    h = (unsigned)__bfloat16_as_ushort(bx) | ((unsigned)__bfloat16_as_ushort(by) << 16);
    l = pack2bf(x - __bfloat162float(bx), y - __bfloat162float(by));
}
__device__ __forceinline__ void ldmx2(unsigned& r0, unsigned& r1, unsigned a) {
    asm volatile("ldmatrix.sync.aligned.m8n8.x2.shared.b16 {%0,%1}, [%2];"
                 : "=r"(r0), "=r"(r1) : "r"(a));
}
__device__ __forceinline__ void ldmx2t(unsigned& r0, unsigned& r1, unsigned a) {
    asm volatile("ldmatrix.sync.aligned.m8n8.x2.trans.shared.b16 {%0,%1}, [%2];"
                 : "=r"(r0), "=r"(r1) : "r"(a));
}
__device__ __forceinline__ void ldmx4(unsigned* r, unsigned a) {
    asm volatile("ldmatrix.sync.aligned.m8n8.x4.shared.b16 {%0,%1,%2,%3}, [%4];"
                 : "=r"(r[0]), "=r"(r[1]), "=r"(r[2]), "=r"(r[3]) : "r"(a));
}
__device__ __forceinline__ void mma16816(float* d, const unsigned* a,
                                         unsigned b0, unsigned b1) {
    asm volatile(
        "mma.sync.aligned.m16n8k16.row.col.f32.bf16.bf16.f32 "
        "{%0,%1,%2,%3},{%4,%5,%6,%7},{%8,%9},{%0,%1,%2,%3};"
        : "+f"(d[0]), "+f"(d[1]), "+f"(d[2]), "+f"(d[3])
        : "r"(a[0]), "r"(a[1]), "r"(a[2]), "r"(a[3]), "r"(b0), "r"(b1));
}
__device__ __forceinline__ void cpasync16(unsigned dst, const void* src) {
    asm volatile("cp.async.cg.shared.global [%0], [%1], 16;"
                 :: "r"(dst), "l"(src));
}
__device__ __forceinline__ void cp_commit() {
    asm volatile("cp.async.commit_group;");
}
__device__ __forceinline__ void cp_wait0() {
    asm volatile("cp.async.wait_group 0;");
}

// ---------------- tensor-core GEMM (bf16 hi/lo split, fp32 accumulate) -------
// C[M,N] = A[M,K] @ W[K,N] (+bias)(+residual).  128x128 CTA tile, BK=64.
// kvsplit: instead of fp32 C, write bf16 hi/lo split to g_kh/g_kl (n<512)
// or g_vh/g_vl (n>=512), layout [tok][512].
#define ASTR 72
#define WSTR 136
#define GEMM_SMEM ((2 * 128 * ASTR + 2 * 64 * WSTR) * 2)   // 71680 B

__global__ __launch_bounds__(256)
void tgemm_kernel(const float* __restrict__ A, const float* __restrict__ W,
                  float* __restrict__ C, int M, int N, int K,
                  const float* __restrict__ bias,
                  const float* __restrict__ residual,
                  int kvsplit)
{
    extern __shared__ __nv_bfloat16 sg[];
    __nv_bfloat16* Ah = sg;
    __nv_bfloat16* Al = Ah + 128 * ASTR;
    __nv_bfloat16* Wh = Al + 128 * ASTR;
    __nv_bfloat16* Wl = Wh + 64 * WSTR;

    const int tid = threadIdx.x;
    const int w = tid >> 5, lane = tid & 31;
    const int wm = w >> 2, wn = w & 3;
    const int m0 = blockIdx.y * 128, n0 = blockIdx.x * 128;
    const int g = lane >> 2, tc = lane & 3;
    const int lr15 = lane & 15;

    float acc[4][4][4];
    #pragma unroll
    for (int mt = 0; mt < 4; mt++)
        #pragma unroll
        for (int nt = 0; nt < 4; nt++) {
            acc[mt][nt][0] = 0.0f; acc[mt][nt][1] = 0.0f;
            acc[mt][nt][2] = 0.0f; acc[mt][nt][3] = 0.0f;
        }

    const int ar  = tid >> 4, ac4 = (tid & 15) << 2;   // A stage: 16 rows x 64 cols
    const int wr  = tid >> 5, wc4 = (tid & 31) << 2;   // W stage: 8 rows x 128 cols

    for (int kb = 0; kb < K; kb += 64) {
        __syncthreads();
        // ---- stage A[128][64] as bf16 hi/lo ----
        #pragma unroll
        for (int p = 0; p < 8; p++) {
            const int row = ar + p * 16;
            float4 a = *(const float4*)(A + (size_t)(m0 + row) * K + kb + ac4);
            unsigned h0, l0, h1, l1;
            split2(a.x, a.y, h0, l0); split2(a.z, a.w, h1, l1);
            *(unsigned*)&Ah[row * ASTR + ac4]     = h0;
            *(unsigned*)&Ah[row * ASTR + ac4 + 2] = h1;
            *(unsigned*)&Al[row * ASTR + ac4]     = l0;
            *(unsigned*)&Al[row * ASTR + ac4 + 2] = l1;
        }
        // ---- stage W[64][128] as bf16 hi/lo ----
        #pragma unroll
        for (int p = 0; p < 8; p++) {
            const int row = wr + p * 8;
            float4 v = *(const float4*)(W + (size_t)(kb + row) * N + n0 + wc4);
            unsigned h0, l0, h1, l1;
            split2(v.x, v.y, h0, l0); split2(v.z, v.w, h1, l1);
            *(unsigned*)&Wh[row * WSTR + wc4]     = h0;
            *(unsigned*)&Wh[row * WSTR + wc4 + 2] = h1;
            *(unsigned*)&Wl[row * WSTR + wc4]     = l0;
            *(unsigned*)&Wl[row * WSTR + wc4 + 2] = l1;
        }
        __syncthreads();

        #pragma unroll
        for (int ks = 0; ks < 4; ks++) {
            unsigned bh[4][2], bl[4][2];
            #pragma unroll
            for (int nt = 0; nt < 4; nt++) {
                const int off = (ks * 16 + lr15) * WSTR + wn * 32 + nt * 8;
                ldmx2t(bh[nt][0], bh[nt][1], sptr(&Wh[off]));
                ldmx2t(bl[nt][0], bl[nt][1], sptr(&Wl[off]));
            }
            #pragma unroll
            for (int mt = 0; mt < 4; mt++) {
                unsigned ahf[4], alf[4];
                const int aoff = (wm * 64 + mt * 16 + lr15) * ASTR
                               + ks * 16 + 8 * (lane >> 4);
                ldmx4(ahf, sptr(&Ah[aoff]));
                ldmx4(alf, sptr(&Al[aoff]));
                #pragma unroll
                for (int nt = 0; nt < 4; nt++) {
                    mma16816(acc[mt][nt], ahf, bh[nt][0], bh[nt][1]);
                    mma16816(acc[mt][nt], ahf, bl[nt][0], bl[nt][1]);
                    mma16816(acc[mt][nt], alf, bh[nt][0], bh[nt][1]);
                }
            }
        }
    }

    if (kvsplit) {
        // write bf16 hi/lo split directly (K part: n<512, V part: n>=512)
        const int vpart = (n0 >= 512);
        #pragma unroll
        for (int mt = 0; mt < 4; mt++) {
            const int row0 = m0 + wm * 64 + mt * 16 + g;
            #pragma unroll
            for (int nt = 0; nt < 4; nt++) {
                const int col = n0 + wn * 32 + nt * 8 + 2 * tc - (vpart ? 512 : 0);
                unsigned h0, l0, h1, l1;
                split2(acc[mt][nt][0], acc[mt][nt][1], h0, l0);
                split2(acc[mt][nt][2], acc[mt][nt][3], h1, l1);
                const size_t p0 = (size_t)row0 * 512 + col;
                const size_t p8 = (size_t)(row0 + 8) * 512 + col;
                if (vpart) {
                    *(unsigned*)&g_vh[p0] = h0; *(unsigned*)&g_vl[p0] = l0;
                    *(unsigned*)&g_vh[p8] = h1; *(unsigned*)&g_vl[p8] = l1;
                } else {
                    *(unsigned*)&g_kh[p0] = h0; *(unsigned*)&g_kl[p0] = l0;
                    *(unsigned*)&g_kh[p8] = h1; *(unsigned*)&g_kl[p8] = l1;
                }
            }
        }
        return;
    }

    // ---- epilogue: bias + residual, fp32 store ----
    #pragma unroll
    for (int mt = 0; mt < 4; mt++) {
        const int row0 = m0 + wm * 64 + mt * 16 + g;
        #pragma unroll
        for (int nt = 0; nt < 4; nt++) {
            const int col = n0 + wn * 32 + nt * 8 + 2 * tc;
            float2 c0 = make_float2(acc[mt][nt][0], acc[mt][nt][1]);
            float2 c1 = make_float2(acc[mt][nt][2], acc[mt][nt][3]);
            if (bias) {
                float2 bb = *(const float2*)(bias + col);
                c0.x += bb.x; c0.y += bb.y; c1.x += bb.x; c1.y += bb.y;
            }
            if (residual) {
                float2 r0 = *(const float2*)(residual + (size_t)row0 * N + col);
                float2 r1 = *(const float2*)(residual + (size_t)(row0 + 8) * N + col);
                c0.x += r0.x; c0.y += r0.y; c1.x += r1.x; c1.y += r1.y;
            }
            *(float2*)(C + (size_t)row0 * N + col) = c0;
            *(float2*)(C + (size_t)(row0 + 8) * N + col) = c1;
        }
    }
}

// ---------------- flash attention: mma.sync bf16 hi/lo, cp.async double-buf --
// 256 threads = 8 warps. Tile 128q x 128k. Warp w owns q rows [16w,16w+16).
// K/V pre-split bf16 hi/lo in gmem; staged via cp.async with 2 smem stages.
#define KSTR 72
#define STG (128 * KSTR)                       // bf16 elems per array per stage
#define ATTN_SMEM (2 * 4 * STG * 2)            // 147456 B

__global__ __launch_bounds__(256)
void attn_kernel(const float* __restrict__ bias,
                 const float* __restrict__ gamma_f)
{
    extern __shared__ __nv_bfloat16 smem_bf[];

    const int tid  = threadIdx.x;
    const int w    = tid >> 5;
    const int lane = tid & 31;
    const int g    = lane >> 2, tc = lane & 3;
    const int qt = blockIdx.x, h = blockIdx.y, b = blockIdx.z;
    const float gam = gamma_f[h];
    const int nq0 = b * S_LEN + qt * 128;
    const int qr  = w * 16 + g;

    // cp.async mapping: 2 threads per row, 64B (4x16B) per thread per array
    const int srow  = tid >> 1;
    const int shalf = (tid & 1) * 32;           // bf16 element offset in row

    // ---- Q fragments straight from gmem (scaled by 0.125, split hi/lo) ----
    unsigned aqh[4][4], aql[4][4];
    {
        const float* qb = g_q + (size_t)(nq0 + qr) * D_EMB + h * D_HEAD;
        #pragma unroll
        for (int ks = 0; ks < 4; ks++) {
            const float* p0 = qb + ks * 16 + 2 * tc;
            float2 f0 = *(const float2*)(p0);
            float2 f1 = *(const float2*)(p0 + 8 * D_EMB);
            float2 f2 = *(const float2*)(p0 + 8);
            float2 f3 = *(const float2*)(p0 + 8 * D_EMB + 8);
            split2(f0.x * 0.125f, f0.y * 0.125f, aqh[ks][0], aql[ks][0]);
            split2(f1.x * 0.125f, f1.y * 0.125f, aqh[ks][1], aql[ks][1]);
            split2(f2.x * 0.125f, f2.y * 0.125f, aqh[ks][2], aql[ks][2]);
            split2(f3.x * 0.125f, f3.y * 0.125f, aqh[ks][3], aql[ks][3]);
        }
    }

    // stage kt's K/V hi/lo into buffer buf via cp.async (16 x 16B per thread)
    auto stage = [&](int kt, int buf) {
        const size_t nk = (size_t)(b * S_LEN + kt * 128 + srow);
        const size_t so = nk * 512 + h * 64 + shalf;
        __nv_bfloat16* base = smem_bf + (size_t)buf * 4 * STG;
        const unsigned doff = (srow * KSTR + shalf) * 2;    // bytes
        const unsigned dkh = sptr(base) + doff;
        const unsigned dkl = dkh + STG * 2;
        const unsigned dvh = dkl + STG * 2;
        const unsigned dvl = dvh + STG * 2;
        #pragma unroll
        for (int i = 0; i < 4; i++) {
            cpasync16(dkh + i * 16, g_kh + so + i * 8);
            cpasync16(dkl + i * 16, g_kl + so + i * 8);
            cpasync16(dvh + i * 16, g_vh + so + i * 8);
            cpasync16(dvl + i * 16, g_vl + so + i * 8);
        }
        cp_commit();
    };

    stage(0, 0);

    float oacc[8][4];
    #pragma unroll
    for (int i = 0; i < 8; i++) { oacc[i][0]=0; oacc[i][1]=0; oacc[i][2]=0; oacc[i][3]=0; }
    float m_g = -1e30f, m_g8 = -1e30f, l_g = 0.0f, l_g8 = 0.0f;

    const int lr7 = lane & 7, lsel = (lane >> 3) & 1, lr15 = lane & 15;
    const int NKT = S_LEN / 128;

    for (int kt = 0; kt < NKT; kt++) {
        const int buf = kt & 1;
        cp_wait0();
        __syncthreads();
        if (kt + 1 < NKT) stage(kt + 1, buf ^ 1);

        __nv_bfloat16* Kh = smem_bf + (size_t)buf * 4 * STG;
        __nv_bfloat16* Kl = Kh + STG;
        __nv_bfloat16* Vh = Kl + STG;
        __nv_bfloat16* Vl = Vh + STG;

        // ---- S = Q K^T via mma (hi*hi + hi*lo + lo*hi) ----
        float sacc[16][4];
        #pragma unroll
        for (int nt = 0; nt < 16; nt++) {
            sacc[nt][0]=0; sacc[nt][1]=0; sacc[nt][2]=0; sacc[nt][3]=0;
        }
        #pragma unroll
        for (int nt = 0; nt < 16; nt++) {
            #pragma unroll
            for (int ks = 0; ks < 4; ks++) {
                const int off = (nt * 8 + lr7) * KSTR + ks * 16 + 8 * lsel;
                unsigned bh0, bh1, bl0, bl1;
                ldmx2(bh0, bh1, sptr(&Kh[off]));
                ldmx2(bl0, bl1, sptr(&Kl[off]));
                mma16816(sacc[nt], aqh[ks], bh0, bh1);
                mma16816(sacc[nt], aqh[ks], bl0, bl1);
                mma16816(sacc[nt], aql[ks], bh0, bh1);
            }
        }

        // ---- gamma*bias + mask (register-resident) ----
        const int ql0 = qt * 128 + w * 16 + g;
        const float* brow0 = bias + ((size_t)b * S_LEN + ql0) * S_LEN + kt * 128;
        const float* brow8 = brow0 + (size_t)8 * S_LEN;
        const float* mrow  = g_maskf + b * S_LEN + kt * 128;
        #pragma unroll
        for (int nt = 0; nt < 16; nt++) {
            const int col = nt * 8 + 2 * tc;
            float2 mk = *(const float2*)(mrow + col);
            float2 b0 = *(const float2*)(brow0 + col);
            float2 b8 = *(const float2*)(brow8 + col);
            sacc[nt][0] = (mk.x != 0.0f) ? -1e9f : fmaf(gam, b0.x, sacc[nt][0]);
            sacc[nt][1] = (mk.y != 0.0f) ? -1e9f : fmaf(gam, b0.y, sacc[nt][1]);
            sacc[nt][2] = (mk.x != 0.0f) ? -1e9f : fmaf(gam, b8.x, sacc[nt][2]);
            sacc[nt][3] = (mk.y != 0.0f) ? -1e9f : fmaf(gam, b8.y, sacc[nt][3]);
        }

        // ---- online softmax in registers (quad shfl) ----
        float t0 = -1e30f, t8 = -1e30f;
        #pragma unroll
        for (int nt = 0; nt < 16; nt++) {
            t0 = fmaxf(t0, fmaxf(sacc[nt][0], sacc[nt][1]));
            t8 = fmaxf(t8, fmaxf(sacc[nt][2], sacc[nt][3]));
        }
        t0 = fmaxf(t0, __shfl_xor_sync(0xffffffffu, t0, 1));
        t0 = fmaxf(t0, __shfl_xor_sync(0xffffffffu, t0, 2));
        t8 = fmaxf(t8, __shfl_xor_sync(0xffffffffu, t8, 1));
        t8 = fmaxf(t8, __shfl_xor_sync(0xffffffffu, t8, 2));
        const float mn0 = fmaxf(m_g, t0), mn8 = fmaxf(m_g8, t8);
        const float cor0 = __expf(m_g - mn0), cor8 = __expf(m_g8 - mn8);
        m_g = mn0; m_g8 = mn8;

        float ps0 = 0.0f, ps8 = 0.0f;
        unsigned phx[16], plx[16], phz[16], plz[16];
        #pragma unroll
        for (int nt = 0; nt < 16; nt++) {
            float e0 = __expf(sacc[nt][0] - mn0);
            float e1 = __expf(sacc[nt][1] - mn0);
            float e2 = __expf(sacc[nt][2] - mn8);
            float e3 = __expf(sacc[nt][3] - mn8);
            ps0 += e0 + e1; ps8 += e2 + e3;
            split2(e0, e1, phx[nt], plx[nt]);
            split2(e2, e3, phz[nt], plz[nt]);
        }
        ps0 += __shfl_xor_sync(0xffffffffu, ps0, 1);
        ps0 += __shfl_xor_sync(0xffffffffu, ps0, 2);
        ps8 += __shfl_xor_sync(0xffffffffu, ps8, 1);
        ps8 += __shfl_xor_sync(0xffffffffu, ps8, 2);
        l_g  = l_g  * cor0 + ps0;
        l_g8 = l_g8 * cor8 + ps8;

        #pragma unroll
        for (int i = 0; i < 8; i++) {
            oacc[i][0] *= cor0; oacc[i][1] *= cor0;
            oacc[i][2] *= cor8; oacc[i][3] *= cor8;
        }

        // ---- O += P @ V ----
        #pragma unroll
        for (int nt2 = 0; nt2 < 8; nt2++) {
            #pragma unroll
            for (int kp = 0; kp < 8; kp++) {
                const unsigned ap[4] = { phx[2*kp], phz[2*kp], phx[2*kp+1], phz[2*kp+1] };
                const unsigned al[4] = { plx[2*kp], plz[2*kp], plx[2*kp+1], plz[2*kp+1] };
                const int off = (kp * 16 + lr15) * KSTR + nt2 * 8;
                unsigned bh0, bh1, bl0, bl1;
                ldmx2t(bh0, bh1, sptr(&Vh[off]));
                ldmx2t(bl0, bl1, sptr(&Vl[off]));
                mma16816(oacc[nt2], ap, bh0, bh1);
                mma16816(oacc[nt2], ap, bl0, bl1);
                mma16816(oacc[nt2], al, bh0, bh1);
            }
        }
    }

    // ---- epilogue: normalize and store ----
    const float inv0 = 1.0f / l_g, inv8 = 1.0f / l_g8;
    float* ob = g_att + (size_t)(nq0 + qr) * D_EMB + h * D_HEAD;
    #pragma unroll
    for (int nt2 = 0; nt2 < 8; nt2++) {
        const int col = nt2 * 8 + 2 * tc;
        *(float2*)(ob + col) = make_float2(oacc[nt2][0] * inv0, oacc[nt2][1] * inv0);
        *(float2*)(ob + (size_t)8 * D_EMB + col) =
            make_float2(oacc[nt2][2] * inv8, oacc[nt2][3] * inv8);
    }
}

// ---------------- layernorm: one warp per row of 512 -------------------------
__global__ void ln_kernel(const float* __restrict__ y,
                          const float* __restrict__ lng,
                          const float* __restrict__ lnb,
                          float* __restrict__ out)
{
    const int warp = threadIdx.x >> 5, lane = threadIdx.x & 31;
    const int row = blockIdx.x * 8 + warp;
    const float* yr = y + (size_t)row * D_EMB;

    float v[16];
    #pragma unroll
    for (int c = 0; c < 4; c++)
        *(float4*)(v + c * 4) = *(const float4*)(yr + c * 128 + lane * 4);

    float s = 0.0f;
    #pragma unroll
    for (int e = 0; e < 16; e++) s += v[e];
    #pragma unroll
    for (int off = 16; off > 0; off >>= 1) s += __shfl_xor_sync(0xffffffffu, s, off);
    const float mu = s * (1.0f / 512.0f);

    float sq = 0.0f;
    #pragma unroll
    for (int e = 0; e < 16; e++) { const float d = v[e] - mu; sq = fmaf(d, d, sq); }
    #pragma unroll
    for (int off = 16; off > 0; off >>= 1) sq += __shfl_xor_sync(0xffffffffu, sq, off);
    const float rstd = rsqrtf(sq * (1.0f / 512.0f) + 1e-5f);

    #pragma unroll
    for (int c = 0; c < 4; c++) {
        const int col = c * 128 + lane * 4;
        float4 gg = *(const float4*)(lng + col);
        float4 bb = *(const float4*)(lnb + col);
        float4 o;
        o.x = (v[c*4+0] - mu) * rstd * gg.x + bb.x;
        o.y = (v[c*4+1] - mu) * rstd * gg.y + bb.y;
        o.z = (v[c*4+2] - mu) * rstd * gg.z + bb.z;
        o.w = (v[c*4+3] - mu) * rstd * gg.w + bb.w;
        *(float4*)(out + (size_t)row * D_EMB + col) = o;
    }
}

// ---------------- launch ------------------------------------------------------
extern "C" void kernel_launch(void* const* d_in, const int* in_sizes, int n_in,
                              void* d_out, int out_size)
{
    (void)in_sizes; (void)n_in; (void)out_size;
    const float* x_p     = (const float*)d_in[0];
    const float* x_pcre  = (const float*)d_in[1];
    const float* bias    = (const float*)d_in[2];
    const void*  mask    = d_in[3];
    const float* Wq      = (const float*)d_in[4];
    const float* Wkv     = (const float*)d_in[5];
    const float* Wff     = (const float*)d_in[6];
    const float* bff     = (const float*)d_in[7];
    const float* gamma_f = (const float*)d_in[8];
    const float* ln_g    = (const float*)d_in[9];
    const float* ln_b    = (const float*)d_in[10];
    float* out = (float*)d_out;

    float *gq, *gatt, *gy, *gmf;
    cudaGetSymbolAddress((void**)&gq,  g_q);
    cudaGetSymbolAddress((void**)&gatt,g_att);
    cudaGetSymbolAddress((void**)&gy,  g_y);
    cudaGetSymbolAddress((void**)&gmf, g_maskf);

    cudaFuncSetAttribute(attn_kernel, cudaFuncAttributeMaxDynamicSharedMemorySize,
                         ATTN_SMEM);
    cudaFuncSetAttribute(tgemm_kernel, cudaFuncAttributeMaxDynamicSharedMemorySize,
                         GEMM_SMEM);

    mask_expand_kernel<<<1, 256>>>(mask, gmf);
    tgemm_kernel<<<dim3(4, 128), 256, GEMM_SMEM>>>(x_p,    Wq,  gq,     NTOK,  512, 512,
                                                   nullptr, nullptr, 0);
    tgemm_kernel<<<dim3(8, 128), 256, GEMM_SMEM>>>(x_pcre, Wkv, nullptr, NTOK, 1024, 512,
                                                   nullptr, nullptr, 1);
    attn_kernel<<<dim3(S_LEN / 128, H_NUM, B_DIM), 256, ATTN_SMEM>>>(bias, gamma_f);
    tgemm_kernel<<<dim3(4, 128), 256, GEMM_SMEM>>>(gatt,   Wff, gy,     NTOK,  512, 512,
                                                   bff, x_p, 0);
    ln_kernel<<<NTOK / 8, 256>>>(gy, ln_g, ln_b, out);
}

// round 14
// speedup vs baseline: 2.0471x; 1.1903x over previous
#include <cuda_runtime.h>
#include <cuda_bf16.h>
#include <cstdint>
#include <cstddef>

#define B_DIM 8
#define S_LEN 2048
#define D_EMB 512
#define H_NUM 8
#define D_HEAD 64
#define NTOK (B_DIM * S_LEN)          // 16384

// ---------------- scratch (static device globals; no runtime alloc) ----------
__device__ float g_q  [(size_t)NTOK * D_EMB];        // 32 MB
__device__ float g_att[(size_t)NTOK * D_EMB];        // 32 MB
__device__ float g_y  [(size_t)NTOK * D_EMB];        // 32 MB
__device__ float g_maskf[B_DIM * S_LEN];             // 64 KB
// pre-split bf16 hi/lo K and V, layout [tok][H*64]
__device__ __nv_bfloat16 g_kh[(size_t)NTOK * 512];   // 16 MB
__device__ __nv_bfloat16 g_kl[(size_t)NTOK * 512];
__device__ __nv_bfloat16 g_vh[(size_t)NTOK * 512];
__device__ __nv_bfloat16 g_vl[(size_t)NTOK * 512];

// ---------------- mask dtype detection + expansion ---------------------------
__global__ void mask_expand_kernel(const void* __restrict__ mraw,
                                   float* __restrict__ mf)
{
    const int tid = threadIdx.x;
    const unsigned int* w = (const unsigned int*)mraw;
    int lf_u8 = 0, lf_i32 = 0, lf_f32 = 0, lf_b16 = 0;
    for (int i = tid; i < 4096; i += 256) {
        unsigned int x = w[i];
        if (x == 0u) continue;
        if (x == 0x3F800000u) { lf_f32 = 1; continue; }          // fp32 1.0
        if (x == 0x00003F80u || x == 0x3F803F80u) { lf_b16 = 1; continue; }
        if (x == 1u) { lf_i32 = 1; continue; }
        bool u8ok = true;
        #pragma unroll
        for (int s = 0; s < 32; s += 8) {
            unsigned int byte = (x >> s) & 0xFFu;
            if (byte > 1u) u8ok = false;
        }
        if (u8ok) lf_u8 = 1;
    }
    int any_b16 = __syncthreads_or(lf_b16);
    int any_f32 = __syncthreads_or(lf_f32);
    int any_u8  = __syncthreads_or(lf_u8);
    int any_i32 = __syncthreads_or(lf_i32);

    int mode;                 // 0=u8, 1=i32, 2=f32, 3=bf16
    if (any_b16)      mode = 3;
    else if (any_f32) mode = 2;
    else if (any_u8)  mode = 0;
    else if (any_i32) mode = 1;
    else              mode = 0;

    for (int j = tid; j < B_DIM * S_LEN; j += 256) {
        bool m;
        if (mode == 0)      m = ((const unsigned char*) mraw)[j] != 0;
        else if (mode == 1) m = ((const int*)           mraw)[j] != 0;
        else if (mode == 2) m = ((const float*)         mraw)[j] != 0.0f;
        else                m = ((const unsigned short*)mraw)[j] != 0;
        mf[j] = m ? 1.0f : 0.0f;
    }
}

// ---------------- tensor-core helpers ----------------------------------------
__device__ __forceinline__ unsigned sptr(const void* p) {
    return (unsigned)__cvta_generic_to_shared(p);
}
__device__ __forceinline__ unsigned pack2bf(float x, float y) {
    unsigned lo = (unsigned)__bfloat16_as_ushort(__float2bfloat16_rn(x));
    unsigned hi = (unsigned)__bfloat16_as_ushort(__float2bfloat16_rn(y));
    return lo | (hi << 16);
}
// split (x,y) into bf16 hi pair + bf16 residual-lo pair
__device__ __forceinline__ void split2(float x, float y, unsigned& h, unsigned& l) {
    __nv_bfloat16 bx = __float2bfloat16_rn(x);
    __nv_bfloat16 by = __float2bfloat16_rn(y);
    h = (unsigned)__bfloat16_as_ushort(bx) | ((unsigned)__bfloat16_as_ushort(by) << 16);
    l = pack2bf(x - __bfloat162float(bx), y - __bfloat162float(by));
}
__device__ __forceinline__ void ldmx2(unsigned& r0, unsigned& r1, unsigned a) {
    asm volatile("ldmatrix.sync.aligned.m8n8.x2.shared.b16 {%0,%1}, [%2];"
                 : "=r"(r0), "=r"(r1) : "r"(a));
}
__device__ __forceinline__ void ldmx2t(unsigned& r0, unsigned& r1, unsigned a) {
    asm volatile("ldmatrix.sync.aligned.m8n8.x2.trans.shared.b16 {%0,%1}, [%2];"
                 : "=r"(r0), "=r"(r1) : "r"(a));
}
__device__ __forceinline__ void ldmx4(unsigned* r, unsigned a) {
    asm volatile("ldmatrix.sync.aligned.m8n8.x4.shared.b16 {%0,%1,%2,%3}, [%4];"
                 : "=r"(r[0]), "=r"(r[1]), "=r"(r[2]), "=r"(r[3]) : "r"(a));
}
__device__ __forceinline__ void mma16816(float* d, const unsigned* a,
                                         unsigned b0, unsigned b1) {
    asm volatile(
        "mma.sync.aligned.m16n8k16.row.col.f32.bf16.bf16.f32 "
        "{%0,%1,%2,%3},{%4,%5,%6,%7},{%8,%9},{%0,%1,%2,%3};"
        : "+f"(d[0]), "+f"(d[1]), "+f"(d[2]), "+f"(d[3])
        : "r"(a[0]), "r"(a[1]), "r"(a[2]), "r"(a[3]), "r"(b0), "r"(b1));
}
__device__ __forceinline__ void cpasync16(unsigned dst, const void* src) {
    asm volatile("cp.async.cg.shared.global [%0], [%1], 16;"
                 :: "r"(dst), "l"(src));
}
__device__ __forceinline__ void cp_commit() {
    asm volatile("cp.async.commit_group;");
}
__device__ __forceinline__ void cp_wait0() {
    asm volatile("cp.async.wait_group 0;");
}

// ---------------- tensor-core GEMM (bf16 hi/lo split, fp32 accumulate) -------
// C[M,N] = A[M,K] @ W[K,N] (+bias)(+residual).  128x128 CTA tile, BK=64.
// kvsplit: instead of fp32 C, write bf16 hi/lo split to g_kh/g_kl (n<512)
// or g_vh/g_vl (n>=512), layout [tok][512].
#define ASTR 72
#define WSTR 136
#define GEMM_SMEM ((2 * 128 * ASTR + 2 * 64 * WSTR) * 2)   // 71680 B

__global__ __launch_bounds__(256)
void tgemm_kernel(const float* __restrict__ A, const float* __restrict__ W,
                  float* __restrict__ C, int M, int N, int K,
                  const float* __restrict__ bias,
                  const float* __restrict__ residual,
                  int kvsplit)
{
    extern __shared__ __nv_bfloat16 sg[];
    __nv_bfloat16* Ah = sg;
    __nv_bfloat16* Al = Ah + 128 * ASTR;
    __nv_bfloat16* Wh = Al + 128 * ASTR;
    __nv_bfloat16* Wl = Wh + 64 * WSTR;

    const int tid = threadIdx.x;
    const int w = tid >> 5, lane = tid & 31;
    const int wm = w >> 2, wn = w & 3;
    const int m0 = blockIdx.y * 128, n0 = blockIdx.x * 128;
    const int g = lane >> 2, tc = lane & 3;
    const int lr15 = lane & 15;

    float acc[4][4][4];
    #pragma unroll
    for (int mt = 0; mt < 4; mt++)
        #pragma unroll
        for (int nt = 0; nt < 4; nt++) {
            acc[mt][nt][0] = 0.0f; acc[mt][nt][1] = 0.0f;
            acc[mt][nt][2] = 0.0f; acc[mt][nt][3] = 0.0f;
        }

    const int ar  = tid >> 4, ac4 = (tid & 15) << 2;   // A stage: 16 rows x 64 cols
    const int wr  = tid >> 5, wc4 = (tid & 31) << 2;   // W stage: 8 rows x 128 cols

    for (int kb = 0; kb < K; kb += 64) {
        __syncthreads();
        // ---- stage A[128][64] as bf16 hi/lo ----
        #pragma unroll
        for (int p = 0; p < 8; p++) {
            const int row = ar + p * 16;
            float4 a = *(const float4*)(A + (size_t)(m0 + row) * K + kb + ac4);
            unsigned h0, l0, h1, l1;
            split2(a.x, a.y, h0, l0); split2(a.z, a.w, h1, l1);
            *(unsigned*)&Ah[row * ASTR + ac4]     = h0;
            *(unsigned*)&Ah[row * ASTR + ac4 + 2] = h1;
            *(unsigned*)&Al[row * ASTR + ac4]     = l0;
            *(unsigned*)&Al[row * ASTR + ac4 + 2] = l1;
        }
        // ---- stage W[64][128] as bf16 hi/lo ----
        #pragma unroll
        for (int p = 0; p < 8; p++) {
            const int row = wr + p * 8;
            float4 v = *(const float4*)(W + (size_t)(kb + row) * N + n0 + wc4);
            unsigned h0, l0, h1, l1;
            split2(v.x, v.y, h0, l0); split2(v.z, v.w, h1, l1);
            *(unsigned*)&Wh[row * WSTR + wc4]     = h0;
            *(unsigned*)&Wh[row * WSTR + wc4 + 2] = h1;
            *(unsigned*)&Wl[row * WSTR + wc4]     = l0;
            *(unsigned*)&Wl[row * WSTR + wc4 + 2] = l1;
        }
        __syncthreads();

        #pragma unroll
        for (int ks = 0; ks < 4; ks++) {
            unsigned bh[4][2], bl[4][2];
            #pragma unroll
            for (int nt = 0; nt < 4; nt++) {
                const int off = (ks * 16 + lr15) * WSTR + wn * 32 + nt * 8;
                ldmx2t(bh[nt][0], bh[nt][1], sptr(&Wh[off]));
                ldmx2t(bl[nt][0], bl[nt][1], sptr(&Wl[off]));
            }
            #pragma unroll
            for (int mt = 0; mt < 4; mt++) {
                unsigned ahf[4], alf[4];
                const int aoff = (wm * 64 + mt * 16 + lr15) * ASTR
                               + ks * 16 + 8 * (lane >> 4);
                ldmx4(ahf, sptr(&Ah[aoff]));
                ldmx4(alf, sptr(&Al[aoff]));
                #pragma unroll
                for (int nt = 0; nt < 4; nt++) {
                    mma16816(acc[mt][nt], ahf, bh[nt][0], bh[nt][1]);
                    mma16816(acc[mt][nt], ahf, bl[nt][0], bl[nt][1]);
                    mma16816(acc[mt][nt], alf, bh[nt][0], bh[nt][1]);
                }
            }
        }
    }

    if (kvsplit) {
        // write bf16 hi/lo split directly (K part: n<512, V part: n>=512)
        const int vpart = (n0 >= 512);
        #pragma unroll
        for (int mt = 0; mt < 4; mt++) {
            const int row0 = m0 + wm * 64 + mt * 16 + g;
            #pragma unroll
            for (int nt = 0; nt < 4; nt++) {
                const int col = n0 + wn * 32 + nt * 8 + 2 * tc - (vpart ? 512 : 0);
                unsigned h0, l0, h1, l1;
                split2(acc[mt][nt][0], acc[mt][nt][1], h0, l0);
                split2(acc[mt][nt][2], acc[mt][nt][3], h1, l1);
                const size_t p0 = (size_t)row0 * 512 + col;
                const size_t p8 = (size_t)(row0 + 8) * 512 + col;
                if (vpart) {
                    *(unsigned*)&g_vh[p0] = h0; *(unsigned*)&g_vl[p0] = l0;
                    *(unsigned*)&g_vh[p8] = h1; *(unsigned*)&g_vl[p8] = l1;
                } else {
                    *(unsigned*)&g_kh[p0] = h0; *(unsigned*)&g_kl[p0] = l0;
                    *(unsigned*)&g_kh[p8] = h1; *(unsigned*)&g_kl[p8] = l1;
                }
            }
        }
        return;
    }

    // ---- epilogue: bias + residual, fp32 store ----
    #pragma unroll
    for (int mt = 0; mt < 4; mt++) {
        const int row0 = m0 + wm * 64 + mt * 16 + g;
        #pragma unroll
        for (int nt = 0; nt < 4; nt++) {
            const int col = n0 + wn * 32 + nt * 8 + 2 * tc;
            float2 c0 = make_float2(acc[mt][nt][0], acc[mt][nt][1]);
            float2 c1 = make_float2(acc[mt][nt][2], acc[mt][nt][3]);
            if (bias) {
                float2 bb = *(const float2*)(bias + col);
                c0.x += bb.x; c0.y += bb.y; c1.x += bb.x; c1.y += bb.y;
            }
            if (residual) {
                float2 r0 = *(const float2*)(residual + (size_t)row0 * N + col);
                float2 r1 = *(const float2*)(residual + (size_t)(row0 + 8) * N + col);
                c0.x += r0.x; c0.y += r0.y; c1.x += r1.x; c1.y += r1.y;
            }
            *(float2*)(C + (size_t)row0 * N + col) = c0;
            *(float2*)(C + (size_t)(row0 + 8) * N + col) = c1;
        }
    }
}

// ---------------- flash attention: mma.sync bf16 hi/lo, TK=64, 2 CTAs/SM ----
// 256 threads = 8 warps, TQ=128 (warp owns 16 q rows), TK=64 k per iteration.
// Small k-tile shrinks sacc/P to 32 regs each -> <=128 regs -> occupancy 2.
// K/V pre-split bf16 hi/lo in gmem; cp.async double-buffered stages.
#define KSTR 72
#define TKA 64
#define STG (TKA * KSTR)                       // bf16 elems per array per stage
#define ATTN_SMEM (2 * 4 * STG * 2)            // 73728 B

__global__ __launch_bounds__(256, 2)
void attn_kernel(const float* __restrict__ bias,
                 const float* __restrict__ gamma_f)
{
    extern __shared__ __nv_bfloat16 smem_bf[];

    const int tid  = threadIdx.x;
    const int w    = tid >> 5;
    const int lane = tid & 31;
    const int g    = lane >> 2, tc = lane & 3;
    const int qt = blockIdx.x, h = blockIdx.y, b = blockIdx.z;
    const float gam = gamma_f[h];
    const int nq0 = b * S_LEN + qt * 128;
    const int qr  = w * 16 + g;

    // cp.async mapping: 4 threads per row (64 rows), 32B per thread per array
    const int srow = tid >> 2;                  // 0..63
    const int scol = (tid & 3) << 4;            // bf16 elem offset 0,16,32,48

    // ---- Q fragments straight from gmem (scaled by 0.125, split hi/lo) ----
    unsigned aqh[4][4], aql[4][4];
    {
        const float* qb = g_q + (size_t)(nq0 + qr) * D_EMB + h * D_HEAD;
        #pragma unroll
        for (int ks = 0; ks < 4; ks++) {
            const float* p0 = qb + ks * 16 + 2 * tc;
            float2 f0 = *(const float2*)(p0);
            float2 f1 = *(const float2*)(p0 + 8 * D_EMB);
            float2 f2 = *(const float2*)(p0 + 8);
            float2 f3 = *(const float2*)(p0 + 8 * D_EMB + 8);
            split2(f0.x * 0.125f, f0.y * 0.125f, aqh[ks][0], aql[ks][0]);
            split2(f1.x * 0.125f, f1.y * 0.125f, aqh[ks][1], aql[ks][1]);
            split2(f2.x * 0.125f, f2.y * 0.125f, aqh[ks][2], aql[ks][2]);
            split2(f3.x * 0.125f, f3.y * 0.125f, aqh[ks][3], aql[ks][3]);
        }
    }

    // stage kt's K/V hi/lo into buffer buf via cp.async (8 x 16B per thread)
    auto stage = [&](int kt, int buf) {
        const size_t nk = (size_t)(b * S_LEN + kt * TKA + srow);
        const size_t so = nk * 512 + h * 64 + scol;
        __nv_bfloat16* base = smem_bf + (size_t)buf * 4 * STG;
        const unsigned doff = (srow * KSTR + scol) * 2;     // bytes
        const unsigned dkh = sptr(base) + doff;
        const unsigned dkl = dkh + STG * 2;
        const unsigned dvh = dkl + STG * 2;
        const unsigned dvl = dvh + STG * 2;
        cpasync16(dkh,      g_kh + so);
        cpasync16(dkh + 16, g_kh + so + 8);
        cpasync16(dkl,      g_kl + so);
        cpasync16(dkl + 16, g_kl + so + 8);
        cpasync16(dvh,      g_vh + so);
        cpasync16(dvh + 16, g_vh + so + 8);
        cpasync16(dvl,      g_vl + so);
        cpasync16(dvl + 16, g_vl + so + 8);
        cp_commit();
    };

    stage(0, 0);

    float oacc[8][4];
    #pragma unroll
    for (int i = 0; i < 8; i++) { oacc[i][0]=0; oacc[i][1]=0; oacc[i][2]=0; oacc[i][3]=0; }
    float m_g = -1e30f, m_g8 = -1e30f, l_g = 0.0f, l_g8 = 0.0f;

    const int lr7 = lane & 7, lsel = (lane >> 3) & 1, lr15 = lane & 15;
    const int NKT = S_LEN / TKA;

    for (int kt = 0; kt < NKT; kt++) {
        const int buf = kt & 1;
        cp_wait0();
        __syncthreads();
        if (kt + 1 < NKT) stage(kt + 1, buf ^ 1);

        __nv_bfloat16* Kh = smem_bf + (size_t)buf * 4 * STG;
        __nv_bfloat16* Kl = Kh + STG;
        __nv_bfloat16* Vh = Kl + STG;
        __nv_bfloat16* Vl = Vh + STG;

        // ---- S = Q K^T via mma (hi*hi + hi*lo + lo*hi) ----
        float sacc[8][4];
        #pragma unroll
        for (int nt = 0; nt < 8; nt++) {
            sacc[nt][0]=0; sacc[nt][1]=0; sacc[nt][2]=0; sacc[nt][3]=0;
        }
        #pragma unroll
        for (int nt = 0; nt < 8; nt++) {
            #pragma unroll
            for (int ks = 0; ks < 4; ks++) {
                const int off = (nt * 8 + lr7) * KSTR + ks * 16 + 8 * lsel;
                unsigned bh0, bh1, bl0, bl1;
                ldmx2(bh0, bh1, sptr(&Kh[off]));
                ldmx2(bl0, bl1, sptr(&Kl[off]));
                mma16816(sacc[nt], aqh[ks], bh0, bh1);
                mma16816(sacc[nt], aqh[ks], bl0, bl1);
                mma16816(sacc[nt], aql[ks], bh0, bh1);
            }
        }

        // ---- gamma*bias + mask (register-resident) ----
        const int ql0 = qt * 128 + w * 16 + g;
        const float* brow0 = bias + ((size_t)b * S_LEN + ql0) * S_LEN + kt * TKA;
        const float* brow8 = brow0 + (size_t)8 * S_LEN;
        const float* mrow  = g_maskf + b * S_LEN + kt * TKA;
        #pragma unroll
        for (int nt = 0; nt < 8; nt++) {
            const int col = nt * 8 + 2 * tc;
            float2 mk = *(const float2*)(mrow + col);
            float2 b0 = *(const float2*)(brow0 + col);
            float2 b8 = *(const float2*)(brow8 + col);
            sacc[nt][0] = (mk.x != 0.0f) ? -1e9f : fmaf(gam, b0.x, sacc[nt][0]);
            sacc[nt][1] = (mk.y != 0.0f) ? -1e9f : fmaf(gam, b0.y, sacc[nt][1]);
            sacc[nt][2] = (mk.x != 0.0f) ? -1e9f : fmaf(gam, b8.x, sacc[nt][2]);
            sacc[nt][3] = (mk.y != 0.0f) ? -1e9f : fmaf(gam, b8.y, sacc[nt][3]);
        }

        // ---- online softmax in registers (quad shfl) ----
        float t0 = -1e30f, t8 = -1e30f;
        #pragma unroll
        for (int nt = 0; nt < 8; nt++) {
            t0 = fmaxf(t0, fmaxf(sacc[nt][0], sacc[nt][1]));
            t8 = fmaxf(t8, fmaxf(sacc[nt][2], sacc[nt][3]));
        }
        t0 = fmaxf(t0, __shfl_xor_sync(0xffffffffu, t0, 1));
        t0 = fmaxf(t0, __shfl_xor_sync(0xffffffffu, t0, 2));
        t8 = fmaxf(t8, __shfl_xor_sync(0xffffffffu, t8, 1));
        t8 = fmaxf(t8, __shfl_xor_sync(0xffffffffu, t8, 2));
        const float mn0 = fmaxf(m_g, t0), mn8 = fmaxf(m_g8, t8);
        const float cor0 = __expf(m_g - mn0), cor8 = __expf(m_g8 - mn8);
        m_g = mn0; m_g8 = mn8;

        float ps0 = 0.0f, ps8 = 0.0f;
        unsigned phx[8], plx[8], phz[8], plz[8];
        #pragma unroll
        for (int nt = 0; nt < 8; nt++) {
            float e0 = __expf(sacc[nt][0] - mn0);
            float e1 = __expf(sacc[nt][1] - mn0);
            float e2 = __expf(sacc[nt][2] - mn8);
            float e3 = __expf(sacc[nt][3] - mn8);
            ps0 += e0 + e1; ps8 += e2 + e3;
            split2(e0, e1, phx[nt], plx[nt]);
            split2(e2, e3, phz[nt], plz[nt]);
        }
        ps0 += __shfl_xor_sync(0xffffffffu, ps0, 1);
        ps0 += __shfl_xor_sync(0xffffffffu, ps0, 2);
        ps8 += __shfl_xor_sync(0xffffffffu, ps8, 1);
        ps8 += __shfl_xor_sync(0xffffffffu, ps8, 2);
        l_g  = l_g  * cor0 + ps0;
        l_g8 = l_g8 * cor8 + ps8;

        #pragma unroll
        for (int i = 0; i < 8; i++) {
            oacc[i][0] *= cor0; oacc[i][1] *= cor0;
            oacc[i][2] *= cor8; oacc[i][3] *= cor8;
        }

        // ---- O += P @ V ----
        #pragma unroll
        for (int nt2 = 0; nt2 < 8; nt2++) {
            #pragma unroll
            for (int kp = 0; kp < 4; kp++) {
                const unsigned ap[4] = { phx[2*kp], phz[2*kp], phx[2*kp+1], phz[2*kp+1] };
                const unsigned al[4] = { plx[2*kp], plz[2*kp], plx[2*kp+1], plz[2*kp+1] };
                const int off = (kp * 16 + lr15) * KSTR + nt2 * 8;
                unsigned bh0, bh1, bl0, bl1;
                ldmx2t(bh0, bh1, sptr(&Vh[off]));
                ldmx2t(bl0, bl1, sptr(&Vl[off]));
                mma16816(oacc[nt2], ap, bh0, bh1);
                mma16816(oacc[nt2], ap, bl0, bl1);
                mma16816(oacc[nt2], al, bh0, bh1);
            }
        }
    }

    // ---- epilogue: normalize and store ----
    const float inv0 = 1.0f / l_g, inv8 = 1.0f / l_g8;
    float* ob = g_att + (size_t)(nq0 + qr) * D_EMB + h * D_HEAD;
    #pragma unroll
    for (int nt2 = 0; nt2 < 8; nt2++) {
        const int col = nt2 * 8 + 2 * tc;
        *(float2*)(ob + col) = make_float2(oacc[nt2][0] * inv0, oacc[nt2][1] * inv0);
        *(float2*)(ob + (size_t)8 * D_EMB + col) =
            make_float2(oacc[nt2][2] * inv8, oacc[nt2][3] * inv8);
    }
}

// ---------------- layernorm: one warp per row of 512 -------------------------
__global__ void ln_kernel(const float* __restrict__ y,
                          const float* __restrict__ lng,
                          const float* __restrict__ lnb,
                          float* __restrict__ out)
{
    const int warp = threadIdx.x >> 5, lane = threadIdx.x & 31;
    const int row = blockIdx.x * 8 + warp;
    const float* yr = y + (size_t)row * D_EMB;

    float v[16];
    #pragma unroll
    for (int c = 0; c < 4; c++)
        *(float4*)(v + c * 4) = *(const float4*)(yr + c * 128 + lane * 4);

    float s = 0.0f;
    #pragma unroll
    for (int e = 0; e < 16; e++) s += v[e];
    #pragma unroll
    for (int off = 16; off > 0; off >>= 1) s += __shfl_xor_sync(0xffffffffu, s, off);
    const float mu = s * (1.0f / 512.0f);

    float sq = 0.0f;
    #pragma unroll
    for (int e = 0; e < 16; e++) { const float d = v[e] - mu; sq = fmaf(d, d, sq); }
    #pragma unroll
    for (int off = 16; off > 0; off >>= 1) sq += __shfl_xor_sync(0xffffffffu, sq, off);
    const float rstd = rsqrtf(sq * (1.0f / 512.0f) + 1e-5f);

    #pragma unroll
    for (int c = 0; c < 4; c++) {
        const int col = c * 128 + lane * 4;
        float4 gg = *(const float4*)(lng + col);
        float4 bb = *(const float4*)(lnb + col);
        float4 o;
        o.x = (v[c*4+0] - mu) * rstd * gg.x + bb.x;
        o.y = (v[c*4+1] - mu) * rstd * gg.y + bb.y;
        o.z = (v[c*4+2] - mu) * rstd * gg.z + bb.z;
        o.w = (v[c*4+3] - mu) * rstd * gg.w + bb.w;
        *(float4*)(out + (size_t)row * D_EMB + col) = o;
    }
}

// ---------------- launch ------------------------------------------------------
extern "C" void kernel_launch(void* const* d_in, const int* in_sizes, int n_in,
                              void* d_out, int out_size)
{
    (void)in_sizes; (void)n_in; (void)out_size;
    const float* x_p     = (const float*)d_in[0];
    const float* x_pcre  = (const float*)d_in[1];
    const float* bias    = (const float*)d_in[2];
    const void*  mask    = d_in[3];
    const float* Wq      = (const float*)d_in[4];
    const float* Wkv     = (const float*)d_in[5];
    const float* Wff     = (const float*)d_in[6];
    const float* bff     = (const float*)d_in[7];
    const float* gamma_f = (const float*)d_in[8];
    const float* ln_g    = (const float*)d_in[9];
    const float* ln_b    = (const float*)d_in[10];
    float* out = (float*)d_out;

    float *gq, *gatt, *gy, *gmf;
    cudaGetSymbolAddress((void**)&gq,  g_q);
    cudaGetSymbolAddress((void**)&gatt,g_att);
    cudaGetSymbolAddress((void**)&gy,  g_y);
    cudaGetSymbolAddress((void**)&gmf, g_maskf);

    cudaFuncSetAttribute(attn_kernel, cudaFuncAttributeMaxDynamicSharedMemorySize,
                         ATTN_SMEM);
    cudaFuncSetAttribute(tgemm_kernel, cudaFuncAttributeMaxDynamicSharedMemorySize,
                         GEMM_SMEM);

    mask_expand_kernel<<<1, 256>>>(mask, gmf);
    tgemm_kernel<<<dim3(4, 128), 256, GEMM_SMEM>>>(x_p,    Wq,  gq,     NTOK,  512, 512,
                                                   nullptr, nullptr, 0);
    tgemm_kernel<<<dim3(8, 128), 256, GEMM_SMEM>>>(x_pcre, Wkv, nullptr, NTOK, 1024, 512,
                                                   nullptr, nullptr, 1);
    attn_kernel<<<dim3(S_LEN / 128, H_NUM, B_DIM), 256, ATTN_SMEM>>>(bias, gamma_f);
    tgemm_kernel<<<dim3(4, 128), 256, GEMM_SMEM>>>(gatt,   Wff, gy,     NTOK,  512, 512,
                                                   bff, x_p, 0);
    ln_kernel<<<NTOK / 8, 256>>>(gy, ln_g, ln_b, out);
}

// round 16
// speedup vs baseline: 2.4710x; 1.2070x over previous
#include <cuda_runtime.h>
#include <cuda_bf16.h>
#include <cstdint>
#include <cstddef>

#define B_DIM 8
#define S_LEN 2048
#define D_EMB 512
#define H_NUM 8
#define D_HEAD 64
#define NTOK (B_DIM * S_LEN)          // 16384

// ---------------- scratch (static device globals; no runtime alloc) ----------
__device__ float g_q  [(size_t)NTOK * D_EMB];        // 32 MB
__device__ float g_att[(size_t)NTOK * D_EMB];        // 32 MB
__device__ float g_y  [(size_t)NTOK * D_EMB];        // 32 MB
__device__ float g_maskf[B_DIM * S_LEN];             // 64 KB
// pre-split bf16 hi/lo K and V, layout [tok][H*64]
__device__ __nv_bfloat16 g_kh[(size_t)NTOK * 512];   // 16 MB
__device__ __nv_bfloat16 g_kl[(size_t)NTOK * 512];
__device__ __nv_bfloat16 g_vh[(size_t)NTOK * 512];
__device__ __nv_bfloat16 g_vl[(size_t)NTOK * 512];

// ---------------- mask dtype detection + expansion ---------------------------
__global__ void mask_expand_kernel(const void* __restrict__ mraw,
                                   float* __restrict__ mf)
{
    const int tid = threadIdx.x;
    const unsigned int* w = (const unsigned int*)mraw;
    int lf_u8 = 0, lf_i32 = 0, lf_f32 = 0, lf_b16 = 0;
    for (int i = tid; i < 4096; i += 256) {
        unsigned int x = w[i];
        if (x == 0u) continue;
        if (x == 0x3F800000u) { lf_f32 = 1; continue; }          // fp32 1.0
        if (x == 0x00003F80u || x == 0x3F803F80u) { lf_b16 = 1; continue; }
        if (x == 1u) { lf_i32 = 1; continue; }
        bool u8ok = true;
        #pragma unroll
        for (int s = 0; s < 32; s += 8) {
            unsigned int byte = (x >> s) & 0xFFu;
            if (byte > 1u) u8ok = false;
        }
        if (u8ok) lf_u8 = 1;
    }
    int any_b16 = __syncthreads_or(lf_b16);
    int any_f32 = __syncthreads_or(lf_f32);
    int any_u8  = __syncthreads_or(lf_u8);
    int any_i32 = __syncthreads_or(lf_i32);

    int mode;                 // 0=u8, 1=i32, 2=f32, 3=bf16
    if (any_b16)      mode = 3;
    else if (any_f32) mode = 2;
    else if (any_u8)  mode = 0;
    else if (any_i32) mode = 1;
    else              mode = 0;

    for (int j = tid; j < B_DIM * S_LEN; j += 256) {
        bool m;
        if (mode == 0)      m = ((const unsigned char*) mraw)[j] != 0;
        else if (mode == 1) m = ((const int*)           mraw)[j] != 0;
        else if (mode == 2) m = ((const float*)         mraw)[j] != 0.0f;
        else                m = ((const unsigned short*)mraw)[j] != 0;
        mf[j] = m ? 1.0f : 0.0f;
    }
}

// ---------------- tensor-core helpers ----------------------------------------
__device__ __forceinline__ unsigned sptr(const void* p) {
    return (unsigned)__cvta_generic_to_shared(p);
}
__device__ __forceinline__ unsigned pack2bf(float x, float y) {
    unsigned lo = (unsigned)__bfloat16_as_ushort(__float2bfloat16_rn(x));
    unsigned hi = (unsigned)__bfloat16_as_ushort(__float2bfloat16_rn(y));
    return lo | (hi << 16);
}
// split (x,y) into bf16 hi pair + bf16 residual-lo pair
__device__ __forceinline__ void split2(float x, float y, unsigned& h, unsigned& l) {
    __nv_bfloat16 bx = __float2bfloat16_rn(x);
    __nv_bfloat16 by = __float2bfloat16_rn(y);
    h = (unsigned)__bfloat16_as_ushort(bx) | ((unsigned)__bfloat16_as_ushort(by) << 16);
    l = pack2bf(x - __bfloat162float(bx), y - __bfloat162float(by));
}
__device__ __forceinline__ void ldmx4(unsigned* r, unsigned a) {
    asm volatile("ldmatrix.sync.aligned.m8n8.x4.shared.b16 {%0,%1,%2,%3}, [%4];"
                 : "=r"(r[0]), "=r"(r[1]), "=r"(r[2]), "=r"(r[3]) : "r"(a));
}
__device__ __forceinline__ void ldmx4t(unsigned* r, unsigned a) {
    asm volatile("ldmatrix.sync.aligned.m8n8.x4.trans.shared.b16 {%0,%1,%2,%3}, [%4];"
                 : "=r"(r[0]), "=r"(r[1]), "=r"(r[2]), "=r"(r[3]) : "r"(a));
}
__device__ __forceinline__ void mma16816(float* d, const unsigned* a,
                                         unsigned b0, unsigned b1) {
    asm volatile(
        "mma.sync.aligned.m16n8k16.row.col.f32.bf16.bf16.f32 "
        "{%0,%1,%2,%3},{%4,%5,%6,%7},{%8,%9},{%0,%1,%2,%3};"
        : "+f"(d[0]), "+f"(d[1]), "+f"(d[2]), "+f"(d[3])
        : "r"(a[0]), "r"(a[1]), "r"(a[2]), "r"(a[3]), "r"(b0), "r"(b1));
}
__device__ __forceinline__ void cpasync16(unsigned dst, const void* src) {
    asm volatile("cp.async.cg.shared.global [%0], [%1], 16;"
                 :: "r"(dst), "l"(src));
}
__device__ __forceinline__ void cp_commit() {
    asm volatile("cp.async.commit_group;");
}
__device__ __forceinline__ void cp_wait0() {
    asm volatile("cp.async.wait_group 0;");
}

// ---------------- tensor-core GEMM (bf16 hi/lo split, fp32 accumulate) -------
// C[M,N] = A[M,K] @ W[K,N] (+bias)(+residual).  128x128 CTA tile, BK=64.
// kvsplit: instead of fp32 C, write bf16 hi/lo split to g_kh/g_kl (n<512)
// or g_vh/g_vl (n>=512), layout [tok][512].
#define ASTR 72
#define WSTR 136
#define GEMM_SMEM ((2 * 128 * ASTR + 2 * 64 * WSTR) * 2)   // 71680 B

__global__ __launch_bounds__(256, 2)
void tgemm_kernel(const float* __restrict__ A, const float* __restrict__ W,
                  float* __restrict__ C, int M, int N, int K,
                  const float* __restrict__ bias,
                  const float* __restrict__ residual,
                  int kvsplit)
{
    extern __shared__ __nv_bfloat16 sg[];
    __nv_bfloat16* Ah = sg;
    __nv_bfloat16* Al = Ah + 128 * ASTR;
    __nv_bfloat16* Wh = Al + 128 * ASTR;
    __nv_bfloat16* Wl = Wh + 64 * WSTR;

    const int tid = threadIdx.x;
    const int w = tid >> 5, lane = tid & 31;
    const int wm = w >> 2, wn = w & 3;
    const int m0 = blockIdx.y * 128, n0 = blockIdx.x * 128;
    const int g = lane >> 2, tc = lane & 3;
    const int lr15 = lane & 15;
    const int lq8 = (lane >> 4) << 3;        // 0 or 8 (x4 col-group select)

    float acc[4][4][4];
    #pragma unroll
    for (int mt = 0; mt < 4; mt++)
        #pragma unroll
        for (int nt = 0; nt < 4; nt++) {
            acc[mt][nt][0] = 0.0f; acc[mt][nt][1] = 0.0f;
            acc[mt][nt][2] = 0.0f; acc[mt][nt][3] = 0.0f;
        }

    const int ar  = tid >> 4, ac4 = (tid & 15) << 2;   // A stage: 16 rows x 64 cols
    const int wr  = tid >> 5, wc4 = (tid & 31) << 2;   // W stage: 8 rows x 128 cols

    for (int kb = 0; kb < K; kb += 64) {
        __syncthreads();
        // ---- stage A[128][64] as bf16 hi/lo ----
        #pragma unroll
        for (int p = 0; p < 8; p++) {
            const int row = ar + p * 16;
            float4 a = *(const float4*)(A + (size_t)(m0 + row) * K + kb + ac4);
            unsigned h0, l0, h1, l1;
            split2(a.x, a.y, h0, l0); split2(a.z, a.w, h1, l1);
            *(unsigned*)&Ah[row * ASTR + ac4]     = h0;
            *(unsigned*)&Ah[row * ASTR + ac4 + 2] = h1;
            *(unsigned*)&Al[row * ASTR + ac4]     = l0;
            *(unsigned*)&Al[row * ASTR + ac4 + 2] = l1;
        }
        // ---- stage W[64][128] as bf16 hi/lo ----
        #pragma unroll
        for (int p = 0; p < 8; p++) {
            const int row = wr + p * 8;
            float4 v = *(const float4*)(W + (size_t)(kb + row) * N + n0 + wc4);
            unsigned h0, l0, h1, l1;
            split2(v.x, v.y, h0, l0); split2(v.z, v.w, h1, l1);
            *(unsigned*)&Wh[row * WSTR + wc4]     = h0;
            *(unsigned*)&Wh[row * WSTR + wc4 + 2] = h1;
            *(unsigned*)&Wl[row * WSTR + wc4]     = l0;
            *(unsigned*)&Wl[row * WSTR + wc4 + 2] = l1;
        }
        __syncthreads();

        #pragma unroll
        for (int ks = 0; ks < 4; ks++) {
            // B-fragments for this warp's 4 n-tiles (hi + lo), x4: 2 n-tiles/op
            unsigned bh[4][2], bl[4][2];
            #pragma unroll
            for (int np = 0; np < 2; np++) {
                const int off = (ks * 16 + lr15) * WSTR + wn * 32 + np * 16 + lq8;
                unsigned t[4];
                ldmx4t(t, sptr(&Wh[off]));
                bh[np*2][0] = t[0]; bh[np*2][1] = t[1];
                bh[np*2+1][0] = t[2]; bh[np*2+1][1] = t[3];
                ldmx4t(t, sptr(&Wl[off]));
                bl[np*2][0] = t[0]; bl[np*2][1] = t[1];
                bl[np*2+1][0] = t[2]; bl[np*2+1][1] = t[3];
            }
            #pragma unroll
            for (int mt = 0; mt < 4; mt++) {
                unsigned ahf[4], alf[4];
                const int aoff = (wm * 64 + mt * 16 + lr15) * ASTR
                               + ks * 16 + 8 * (lane >> 4);
                ldmx4(ahf, sptr(&Ah[aoff]));
                ldmx4(alf, sptr(&Al[aoff]));
                #pragma unroll
                for (int nt = 0; nt < 4; nt++) {
                    mma16816(acc[mt][nt], ahf, bh[nt][0], bh[nt][1]);
                    mma16816(acc[mt][nt], ahf, bl[nt][0], bl[nt][1]);
                    mma16816(acc[mt][nt], alf, bh[nt][0], bh[nt][1]);
                }
            }
        }
    }

    if (kvsplit) {
        // write bf16 hi/lo split directly (K part: n<512, V part: n>=512)
        const int vpart = (n0 >= 512);
        #pragma unroll
        for (int mt = 0; mt < 4; mt++) {
            const int row0 = m0 + wm * 64 + mt * 16 + g;
            #pragma unroll
            for (int nt = 0; nt < 4; nt++) {
                const int col = n0 + wn * 32 + nt * 8 + 2 * tc - (vpart ? 512 : 0);
                unsigned h0, l0, h1, l1;
                split2(acc[mt][nt][0], acc[mt][nt][1], h0, l0);
                split2(acc[mt][nt][2], acc[mt][nt][3], h1, l1);
                const size_t p0 = (size_t)row0 * 512 + col;
                const size_t p8 = (size_t)(row0 + 8) * 512 + col;
                if (vpart) {
                    *(unsigned*)&g_vh[p0] = h0; *(unsigned*)&g_vl[p0] = l0;
                    *(unsigned*)&g_vh[p8] = h1; *(unsigned*)&g_vl[p8] = l1;
                } else {
                    *(unsigned*)&g_kh[p0] = h0; *(unsigned*)&g_kl[p0] = l0;
                    *(unsigned*)&g_kh[p8] = h1; *(unsigned*)&g_kl[p8] = l1;
                }
            }
        }
        return;
    }

    // ---- epilogue: bias + residual, fp32 store ----
    #pragma unroll
    for (int mt = 0; mt < 4; mt++) {
        const int row0 = m0 + wm * 64 + mt * 16 + g;
        #pragma unroll
        for (int nt = 0; nt < 4; nt++) {
            const int col = n0 + wn * 32 + nt * 8 + 2 * tc;
            float2 c0 = make_float2(acc[mt][nt][0], acc[mt][nt][1]);
            float2 c1 = make_float2(acc[mt][nt][2], acc[mt][nt][3]);
            if (bias) {
                float2 bb = *(const float2*)(bias + col);
                c0.x += bb.x; c0.y += bb.y; c1.x += bb.x; c1.y += bb.y;
            }
            if (residual) {
                float2 r0 = *(const float2*)(residual + (size_t)row0 * N + col);
                float2 r1 = *(const float2*)(residual + (size_t)(row0 + 8) * N + col);
                c0.x += r0.x; c0.y += r0.y; c1.x += r1.x; c1.y += r1.y;
            }
            *(float2*)(C + (size_t)row0 * N + col) = c0;
            *(float2*)(C + (size_t)(row0 + 8) * N + col) = c1;
        }
    }
}

// ---------------- flash attention: mma.sync bf16 hi/lo, TK=64, 2 CTAs/SM ----
// 256 threads = 8 warps, TQ=128 (warp owns 16 q rows), TK=64 k per iteration.
// ldmatrix.x4 halves shared-load instruction count vs x2.
// K/V pre-split bf16 hi/lo in gmem; cp.async double-buffered stages.
#define KSTR 72
#define TKA 64
#define STG (TKA * KSTR)                       // bf16 elems per array per stage
#define ATTN_SMEM (2 * 4 * STG * 2)            // 73728 B

__global__ __launch_bounds__(256, 2)
void attn_kernel(const float* __restrict__ bias,
                 const float* __restrict__ gamma_f)
{
    extern __shared__ __nv_bfloat16 smem_bf[];

    const int tid  = threadIdx.x;
    const int w    = tid >> 5;
    const int lane = tid & 31;
    const int g    = lane >> 2, tc = lane & 3;
    const int qt = blockIdx.x, h = blockIdx.y, b = blockIdx.z;
    const float gam = gamma_f[h];
    const int nq0 = b * S_LEN + qt * 128;
    const int qr  = w * 16 + g;

    // cp.async mapping: 4 threads per row (64 rows), 32B per thread per array
    const int srow = tid >> 2;                  // 0..63
    const int scol = (tid & 3) << 4;            // bf16 elem offset 0,16,32,48

    // ---- Q fragments straight from gmem (scaled by 0.125, split hi/lo) ----
    unsigned aqh[4][4], aql[4][4];
    {
        const float* qb = g_q + (size_t)(nq0 + qr) * D_EMB + h * D_HEAD;
        #pragma unroll
        for (int ks = 0; ks < 4; ks++) {
            const float* p0 = qb + ks * 16 + 2 * tc;
            float2 f0 = *(const float2*)(p0);
            float2 f1 = *(const float2*)(p0 + 8 * D_EMB);
            float2 f2 = *(const float2*)(p0 + 8);
            float2 f3 = *(const float2*)(p0 + 8 * D_EMB + 8);
            split2(f0.x * 0.125f, f0.y * 0.125f, aqh[ks][0], aql[ks][0]);
            split2(f1.x * 0.125f, f1.y * 0.125f, aqh[ks][1], aql[ks][1]);
            split2(f2.x * 0.125f, f2.y * 0.125f, aqh[ks][2], aql[ks][2]);
            split2(f3.x * 0.125f, f3.y * 0.125f, aqh[ks][3], aql[ks][3]);
        }
    }

    // stage kt's K/V hi/lo into buffer buf via cp.async (8 x 16B per thread)
    auto stage = [&](int kt, int buf) {
        const size_t nk = (size_t)(b * S_LEN + kt * TKA + srow);
        const size_t so = nk * 512 + h * 64 + scol;
        __nv_bfloat16* base = smem_bf + (size_t)buf * 4 * STG;
        const unsigned doff = (srow * KSTR + scol) * 2;     // bytes
        const unsigned dkh = sptr(base) + doff;
        const unsigned dkl = dkh + STG * 2;
        const unsigned dvh = dkl + STG * 2;
        const unsigned dvl = dvh + STG * 2;
        cpasync16(dkh,      g_kh + so);
        cpasync16(dkh + 16, g_kh + so + 8);
        cpasync16(dkl,      g_kl + so);
        cpasync16(dkl + 16, g_kl + so + 8);
        cpasync16(dvh,      g_vh + so);
        cpasync16(dvh + 16, g_vh + so + 8);
        cpasync16(dvl,      g_vl + so);
        cpasync16(dvl + 16, g_vl + so + 8);
        cp_commit();
    };

    stage(0, 0);

    float oacc[8][4];
    #pragma unroll
    for (int i = 0; i < 8; i++) { oacc[i][0]=0; oacc[i][1]=0; oacc[i][2]=0; oacc[i][3]=0; }
    float m_g = -1e30f, m_g8 = -1e30f, l_g = 0.0f, l_g8 = 0.0f;

    const int lr7 = lane & 7, lr15 = lane & 15;
    const int lq8  = (lane >> 4) << 3;          // 0/8 col-group for x4 trans
    const int lk8  = (lane >> 3) << 3;          // 0/8/16/24 col-group for x4
    const int NKT = S_LEN / TKA;

    for (int kt = 0; kt < NKT; kt++) {
        const int buf = kt & 1;
        cp_wait0();
        __syncthreads();
        if (kt + 1 < NKT) stage(kt + 1, buf ^ 1);

        __nv_bfloat16* Kh = smem_bf + (size_t)buf * 4 * STG;
        __nv_bfloat16* Kl = Kh + STG;
        __nv_bfloat16* Vh = Kl + STG;
        __nv_bfloat16* Vl = Vh + STG;

        // ---- S = Q K^T via mma (hi*hi + hi*lo + lo*hi), x4 K loads ----
        float sacc[8][4];
        #pragma unroll
        for (int nt = 0; nt < 8; nt++) {
            sacc[nt][0]=0; sacc[nt][1]=0; sacc[nt][2]=0; sacc[nt][3]=0;
        }
        #pragma unroll
        for (int nt = 0; nt < 8; nt++) {
            #pragma unroll
            for (int ksp = 0; ksp < 2; ksp++) {
                const int off = (nt * 8 + lr7) * KSTR + ksp * 32 + lk8;
                unsigned bh[4], bl[4];
                ldmx4(bh, sptr(&Kh[off]));
                ldmx4(bl, sptr(&Kl[off]));
                mma16816(sacc[nt], aqh[2*ksp],   bh[0], bh[1]);
                mma16816(sacc[nt], aqh[2*ksp],   bl[0], bl[1]);
                mma16816(sacc[nt], aql[2*ksp],   bh[0], bh[1]);
                mma16816(sacc[nt], aqh[2*ksp+1], bh[2], bh[3]);
                mma16816(sacc[nt], aqh[2*ksp+1], bl[2], bl[3]);
                mma16816(sacc[nt], aql[2*ksp+1], bh[2], bh[3]);
            }
        }

        // ---- gamma*bias + mask (register-resident) ----
        const int ql0 = qt * 128 + w * 16 + g;
        const float* brow0 = bias + ((size_t)b * S_LEN + ql0) * S_LEN + kt * TKA;
        const float* brow8 = brow0 + (size_t)8 * S_LEN;
        const float* mrow  = g_maskf + b * S_LEN + kt * TKA;
        #pragma unroll
        for (int nt = 0; nt < 8; nt++) {
            const int col = nt * 8 + 2 * tc;
            float2 mk = *(const float2*)(mrow + col);
            float2 b0 = *(const float2*)(brow0 + col);
            float2 b8 = *(const float2*)(brow8 + col);
            sacc[nt][0] = (mk.x != 0.0f) ? -1e9f : fmaf(gam, b0.x, sacc[nt][0]);
            sacc[nt][1] = (mk.y != 0.0f) ? -1e9f : fmaf(gam, b0.y, sacc[nt][1]);
            sacc[nt][2] = (mk.x != 0.0f) ? -1e9f : fmaf(gam, b8.x, sacc[nt][2]);
            sacc[nt][3] = (mk.y != 0.0f) ? -1e9f : fmaf(gam, b8.y, sacc[nt][3]);
        }

        // ---- online softmax in registers (quad shfl) ----
        float t0 = -1e30f, t8 = -1e30f;
        #pragma unroll
        for (int nt = 0; nt < 8; nt++) {
            t0 = fmaxf(t0, fmaxf(sacc[nt][0], sacc[nt][1]));
            t8 = fmaxf(t8, fmaxf(sacc[nt][2], sacc[nt][3]));
        }
        t0 = fmaxf(t0, __shfl_xor_sync(0xffffffffu, t0, 1));
        t0 = fmaxf(t0, __shfl_xor_sync(0xffffffffu, t0, 2));
        t8 = fmaxf(t8, __shfl_xor_sync(0xffffffffu, t8, 1));
        t8 = fmaxf(t8, __shfl_xor_sync(0xffffffffu, t8, 2));
        const float mn0 = fmaxf(m_g, t0), mn8 = fmaxf(m_g8, t8);
        const float cor0 = __expf(m_g - mn0), cor8 = __expf(m_g8 - mn8);
        m_g = mn0; m_g8 = mn8;

        float ps0 = 0.0f, ps8 = 0.0f;
        unsigned phx[8], plx[8], phz[8], plz[8];
        #pragma unroll
        for (int nt = 0; nt < 8; nt++) {
            float e0 = __expf(sacc[nt][0] - mn0);
            float e1 = __expf(sacc[nt][1] - mn0);
            float e2 = __expf(sacc[nt][2] - mn8);
            float e3 = __expf(sacc[nt][3] - mn8);
            ps0 += e0 + e1; ps8 += e2 + e3;
            split2(e0, e1, phx[nt], plx[nt]);
            split2(e2, e3, phz[nt], plz[nt]);
        }
        ps0 += __shfl_xor_sync(0xffffffffu, ps0, 1);
        ps0 += __shfl_xor_sync(0xffffffffu, ps0, 2);
        ps8 += __shfl_xor_sync(0xffffffffu, ps8, 1);
        ps8 += __shfl_xor_sync(0xffffffffu, ps8, 2);
        l_g  = l_g  * cor0 + ps0;
        l_g8 = l_g8 * cor8 + ps8;

        #pragma unroll
        for (int i = 0; i < 8; i++) {
            oacc[i][0] *= cor0; oacc[i][1] *= cor0;
            oacc[i][2] *= cor8; oacc[i][3] *= cor8;
        }

        // ---- O += P @ V : x4.trans V loads (2 n-tiles per ldmatrix) ----
        #pragma unroll
        for (int kp = 0; kp < 4; kp++) {
            const unsigned ap[4] = { phx[2*kp], phz[2*kp], phx[2*kp+1], phz[2*kp+1] };
            const unsigned al[4] = { plx[2*kp], plz[2*kp], plx[2*kp+1], plz[2*kp+1] };
            #pragma unroll
            for (int np = 0; np < 4; np++) {
                const int off = (kp * 16 + lr15) * KSTR + np * 16 + lq8;
                unsigned bh[4], bl[4];
                ldmx4t(bh, sptr(&Vh[off]));
                ldmx4t(bl, sptr(&Vl[off]));
                mma16816(oacc[2*np],   ap, bh[0], bh[1]);
                mma16816(oacc[2*np],   ap, bl[0], bl[1]);
                mma16816(oacc[2*np],   al, bh[0], bh[1]);
                mma16816(oacc[2*np+1], ap, bh[2], bh[3]);
                mma16816(oacc[2*np+1], ap, bl[2], bl[3]);
                mma16816(oacc[2*np+1], al, bh[2], bh[3]);
            }
        }
    }

    // ---- epilogue: normalize and store ----
    const float inv0 = 1.0f / l_g, inv8 = 1.0f / l_g8;
    float* ob = g_att + (size_t)(nq0 + qr) * D_EMB + h * D_HEAD;
    #pragma unroll
    for (int nt2 = 0; nt2 < 8; nt2++) {
        const int col = nt2 * 8 + 2 * tc;
        *(float2*)(ob + col) = make_float2(oacc[nt2][0] * inv0, oacc[nt2][1] * inv0);
        *(float2*)(ob + (size_t)8 * D_EMB + col) =
            make_float2(oacc[nt2][2] * inv8, oacc[nt2][3] * inv8);
    }
}

// ---------------- layernorm: one warp per row of 512 -------------------------
__global__ void ln_kernel(const float* __restrict__ y,
                          const float* __restrict__ lng,
                          const float* __restrict__ lnb,
                          float* __restrict__ out)
{
    const int warp = threadIdx.x >> 5, lane = threadIdx.x & 31;
    const int row = blockIdx.x * 8 + warp;
    const float* yr = y + (size_t)row * D_EMB;

    float v[16];
    #pragma unroll
    for (int c = 0; c < 4; c++)
        *(float4*)(v + c * 4) = *(const float4*)(yr + c * 128 + lane * 4);

    float s = 0.0f;
    #pragma unroll
    for (int e = 0; e < 16; e++) s += v[e];
    #pragma unroll
    for (int off = 16; off > 0; off >>= 1) s += __shfl_xor_sync(0xffffffffu, s, off);
    const float mu = s * (1.0f / 512.0f);

    float sq = 0.0f;
    #pragma unroll
    for (int e = 0; e < 16; e++) { const float d = v[e] - mu; sq = fmaf(d, d, sq); }
    #pragma unroll
    for (int off = 16; off > 0; off >>= 1) sq += __shfl_xor_sync(0xffffffffu, sq, off);
    const float rstd = rsqrtf(sq * (1.0f / 512.0f) + 1e-5f);

    #pragma unroll
    for (int c = 0; c < 4; c++) {
        const int col = c * 128 + lane * 4;
        float4 gg = *(const float4*)(lng + col);
        float4 bb = *(const float4*)(lnb + col);
        float4 o;
        o.x = (v[c*4+0] - mu) * rstd * gg.x + bb.x;
        o.y = (v[c*4+1] - mu) * rstd * gg.y + bb.y;
        o.z = (v[c*4+2] - mu) * rstd * gg.z + bb.z;
        o.w = (v[c*4+3] - mu) * rstd * gg.w + bb.w;
        *(float4*)(out + (size_t)row * D_EMB + col) = o;
    }
}

// ---------------- launch ------------------------------------------------------
extern "C" void kernel_launch(void* const* d_in, const int* in_sizes, int n_in,
                              void* d_out, int out_size)
{
    (void)in_sizes; (void)n_in; (void)out_size;
    const float* x_p     = (const float*)d_in[0];
    const float* x_pcre  = (const float*)d_in[1];
    const float* bias    = (const float*)d_in[2];
    const void*  mask    = d_in[3];
    const float* Wq      = (const float*)d_in[4];
    const float* Wkv     = (const float*)d_in[5];
    const float* Wff     = (const float*)d_in[6];
    const float* bff     = (const float*)d_in[7];
    const float* gamma_f = (const float*)d_in[8];
    const float* ln_g    = (const float*)d_in[9];
    const float* ln_b    = (const float*)d_in[10];
    float* out = (float*)d_out;

    float *gq, *gatt, *gy, *gmf;
    cudaGetSymbolAddress((void**)&gq,  g_q);
    cudaGetSymbolAddress((void**)&gatt,g_att);
    cudaGetSymbolAddress((void**)&gy,  g_y);
    cudaGetSymbolAddress((void**)&gmf, g_maskf);

    cudaFuncSetAttribute(attn_kernel, cudaFuncAttributeMaxDynamicSharedMemorySize,
                         ATTN_SMEM);
    cudaFuncSetAttribute(tgemm_kernel, cudaFuncAttributeMaxDynamicSharedMemorySize,
                         GEMM_SMEM);

    mask_expand_kernel<<<1, 256>>>(mask, gmf);
    tgemm_kernel<<<dim3(4, 128), 256, GEMM_SMEM>>>(x_p,    Wq,  gq,     NTOK,  512, 512,
                                                   nullptr, nullptr, 0);
    tgemm_kernel<<<dim3(8, 128), 256, GEMM_SMEM>>>(x_pcre, Wkv, nullptr, NTOK, 1024, 512,
                                                   nullptr, nullptr, 1);
    attn_kernel<<<dim3(S_LEN / 128, H_NUM, B_DIM), 256, ATTN_SMEM>>>(bias, gamma_f);
    tgemm_kernel<<<dim3(4, 128), 256, GEMM_SMEM>>>(gatt,   Wff, gy,     NTOK,  512, 512,
                                                   bff, x_p, 0);
    ln_kernel<<<NTOK / 8, 256>>>(gy, ln_g, ln_b, out);
}